// round 4
// baseline (speedup 1.0000x reference)
#include <cuda_runtime.h>
#include <math.h>

// Problem constants
#define NN   32768
#define MULT 256

// ---------------- scratch (allocation-free: __device__ globals) ----------------
__device__ float g_F0 [NN*512];   // [s, |v|] for input x
__device__ float g_V  [NN*768];   // x vectors, planar [n][i][u]
__device__ float g_H1 [NN*512];
__device__ float g_H2 [NN*512];
__device__ float g_G1 [NN*512];
__device__ float g_G2 [NN*512];
__device__ float g_VG1[NN*768];
__device__ float g_VG2[NN*768];
__device__ float g_SL [NN*256];
__device__ float g_SR [NN*256];
__device__ float g_VL [NN*768];
__device__ float g_VR [NN*768];
__device__ float g_F0t[NN*512];
__device__ float g_Vt [NN*768];
__device__ float g_H3 [NN*512];
__device__ float g_G3 [NN*512];
__device__ float g_VG3[NN*768];
__device__ float g_VO3[NN*768];

// ---------------- generic fp32 tiled GEMM ----------------
// C[M,Nc] = act( alpha * A[M,K] @ B[K,Nc] + bias + res )
// A row-major (lda), B row-major (ldb), C row-major (ldc).
// act: 0 = none, 1 = SiLU
#define BM 128
#define BN 128
#define BK 16

__global__ __launch_bounds__(256, 2)
void gemm_f32(const float* __restrict__ A, int lda,
              const float* __restrict__ B, int ldb,
              float* __restrict__ C, int ldc,
              const float* __restrict__ bias,
              const float* __restrict__ res, int ldres,
              int M, int Nc, int K, float alpha, int act)
{
    __shared__ float As[BK][BM + 4];
    __shared__ float Bs[BK][BN + 4];

    const int tid = threadIdx.x;
    const int block_m = blockIdx.y * BM;
    const int block_n = blockIdx.x * BN;
    const int tx = tid & 15;   // 0..15
    const int ty = tid >> 4;   // 0..15

    float acc[8][8];
#pragma unroll
    for (int i = 0; i < 8; i++)
#pragma unroll
        for (int j = 0; j < 8; j++) acc[i][j] = 0.f;

    for (int k0 = 0; k0 < K; k0 += BK) {
        // load A tile 128x16 (512 float4, 2 per thread), store transposed
#pragma unroll
        for (int it = 0; it < 2; it++) {
            int r  = (tid >> 2) + it * 64;       // 0..127
            int c4 = (tid & 3) * 4;              // 0,4,8,12
            float4 a = *reinterpret_cast<const float4*>(
                A + (size_t)(block_m + r) * lda + k0 + c4);
            As[c4 + 0][r] = a.x;
            As[c4 + 1][r] = a.y;
            As[c4 + 2][r] = a.z;
            As[c4 + 3][r] = a.w;
        }
        // load B tile 16x128 (512 float4, 2 per thread)
#pragma unroll
        for (int it = 0; it < 2; it++) {
            int r  = (tid >> 5) + it * 8;        // 0..15
            int c4 = (tid & 31) * 4;             // 0..124
            float4 b = *reinterpret_cast<const float4*>(
                B + (size_t)(k0 + r) * ldb + block_n + c4);
            *reinterpret_cast<float4*>(&Bs[r][c4]) = b;
        }
        __syncthreads();

#pragma unroll
        for (int kk = 0; kk < BK; kk++) {
            float4 a0 = *reinterpret_cast<const float4*>(&As[kk][ty * 4]);
            float4 a1 = *reinterpret_cast<const float4*>(&As[kk][64 + ty * 4]);
            float4 b0 = *reinterpret_cast<const float4*>(&Bs[kk][tx * 4]);
            float4 b1 = *reinterpret_cast<const float4*>(&Bs[kk][64 + tx * 4]);
            float af[8] = {a0.x, a0.y, a0.z, a0.w, a1.x, a1.y, a1.z, a1.w};
            float bf[8] = {b0.x, b0.y, b0.z, b0.w, b1.x, b1.y, b1.z, b1.w};
#pragma unroll
            for (int i = 0; i < 8; i++)
#pragma unroll
                for (int j = 0; j < 8; j++)
                    acc[i][j] = fmaf(af[i], bf[j], acc[i][j]);
        }
        __syncthreads();
    }

    // epilogue
#pragma unroll
    for (int ri = 0; ri < 2; ri++) {
        int rbase = block_m + (ri ? 64 : 0) + ty * 4;
#pragma unroll
        for (int i = 0; i < 4; i++) {
            int row = rbase + i;
#pragma unroll
            for (int ci = 0; ci < 2; ci++) {
                int cbase = block_n + (ci ? 64 : 0) + tx * 4;
#pragma unroll
                for (int j = 0; j < 4; j++) {
                    int col = cbase + j;
                    float v = acc[ri * 4 + i][ci * 4 + j] * alpha;
                    if (bias) v += bias[col];
                    if (res)  v += res[(size_t)row * ldres + col];
                    if (act)  v = v / (1.0f + expf(-v));   // SiLU
                    C[(size_t)row * ldc + col] = v;
                }
            }
        }
    }
}

// ---------------- elementwise kernels ----------------

// x[N,1024] -> F0[N,512]=[s,|v|], V[N,3,256] planar
__global__ void prep_kernel(const float* __restrict__ x,
                            float* __restrict__ F0, float* __restrict__ V)
{
    const int n = blockIdx.x;
    const int u = threadIdx.x;
    const float* xr = x + (size_t)n * 1024;
    float s  = xr[u];
    float v0 = xr[256 + 3 * u + 0];
    float v1 = xr[256 + 3 * u + 1];
    float v2 = xr[256 + 3 * u + 2];
    F0[(size_t)n * 512 + u]       = s;
    F0[(size_t)n * 512 + 256 + u] = sqrtf(v0 * v0 + v1 * v1 + v2 * v2 + 1e-12f);
    size_t vb = ((size_t)3 * n) * 256 + u;
    V[vb]       = v0;
    V[vb + 256] = v1;
    V[vb + 512] = v2;
}

// VG[(3n+i)*256+u] = V[...] * G[n*512 + 256 + u]
__global__ void gate_kernel(const float* __restrict__ V,
                            const float* __restrict__ G,
                            float* __restrict__ VG)
{
    size_t idx = (size_t)blockIdx.x * blockDim.x + threadIdx.x;
    int u = (int)(idx & 255);
    size_t r = idx >> 8;
    size_t n = r / 3;
    VG[idx] = V[idx] * G[n * 512 + 256 + u];
}

// tensor product + resnet(x) + norms for the output gate
__global__ void tp_kernel(const float* __restrict__ SL, const float* __restrict__ VL,
                          const float* __restrict__ SR, const float* __restrict__ VR,
                          const float* __restrict__ F0, const float* __restrict__ V,
                          const float* __restrict__ tpw,
                          float* __restrict__ F0t, float* __restrict__ Vt)
{
    const int n = blockIdx.x;
    const int u = threadIdx.x;
    const size_t b256 = (size_t)n * 256 + u;
    const size_t b512 = (size_t)n * 512 + u;
    const size_t vb   = ((size_t)3 * n) * 256 + u;

    float s1 = SL[b256], s2 = SR[b256];
    float ax = VL[vb], ay = VL[vb + 256], az = VL[vb + 512];
    float bx = VR[vb], by = VR[vb + 256], bz = VR[vb + 512];
    float w0 = tpw[u], w1 = tpw[256 + u], w2 = tpw[512 + u],
          w3 = tpw[768 + u], w4 = tpw[1024 + u];

    const float A0 = 0.44721359549995793f;  // sqrt(1/5)
    const float A1 = 0.77459666924148340f;  // sqrt(3/5)
    const float I3 = 0.57735026918962576f;  // 1/sqrt(3)
    const float I6 = 0.40824829046386302f;  // 1/sqrt(6)

    float dot = ax * bx + ay * by + az * bz;
    float t0 = A0 * (w0 * s1 * s2 + w3 * I3 * dot) + F0[b512];

    float cx = ay * bz - az * by;
    float cy = az * bx - ax * bz;
    float cz = ax * by - ay * bx;
    float k1 = A1 * I3 * w1 * s1;
    float k2 = A1 * I3 * w2 * s2;
    float k4 = A1 * I6 * w4;
    float tx = k1 * bx + k2 * ax + k4 * cx + V[vb];
    float ty = k1 * by + k2 * ay + k4 * cy + V[vb + 256];
    float tz = k1 * bz + k2 * az + k4 * cz + V[vb + 512];

    F0t[b512]       = t0;
    F0t[b512 + 256] = sqrtf(tx * tx + ty * ty + tz * tz + 1e-12f);
    Vt[vb]       = tx;
    Vt[vb + 256] = ty;
    Vt[vb + 512] = tz;
}

// out[n,256+3u+i] = old_fii[...] + VO3[(3n+i)*256+u]
__global__ void final_kernel(const float* __restrict__ VO3,
                             const float* __restrict__ old_fii,
                             float* __restrict__ out)
{
    size_t idx = (size_t)blockIdx.x * blockDim.x + threadIdx.x; // NN*768
    size_t n = idx / 768;
    int j = (int)(idx % 768);
    int u = j / 3;
    int i = j % 3;
    size_t o = n * 1024 + 256 + j;
    out[o] = old_fii[o] + VO3[((size_t)3 * n + i) * 256 + u];
}

// ---------------- host launch ----------------
static inline void launch_gemm(const float* A, int lda, const float* B, int ldb,
                               float* C, int ldc, const float* bias,
                               const float* res, int ldres,
                               int M, int Nc, int K, float alpha, int act)
{
    dim3 grid(Nc / BN, M / BM);
    gemm_f32<<<grid, 256>>>(A, lda, B, ldb, C, ldc, bias, res, ldres,
                            M, Nc, K, alpha, act);
}

extern "C" void kernel_launch(void* const* d_in, const int* in_sizes, int n_in,
                              void* d_out, int out_size)
{
    const float* x       = (const float*)d_in[0];
    const float* old_fii = (const float*)d_in[1];
    const float* ng1_w1 = (const float*)d_in[2];
    const float* ng1_b1 = (const float*)d_in[3];
    const float* ng1_w2 = (const float*)d_in[4];
    const float* ng1_b2 = (const float*)d_in[5];
    const float* ng2_w1 = (const float*)d_in[6];
    const float* ng2_b1 = (const float*)d_in[7];
    const float* ng2_w2 = (const float*)d_in[8];
    const float* ng2_b2 = (const float*)d_in[9];
    const float* ngo_w1 = (const float*)d_in[10];
    const float* ngo_b1 = (const float*)d_in[11];
    const float* ngo_w2 = (const float*)d_in[12];
    const float* ngo_b2 = (const float*)d_in[13];
    const float* lin1_w0 = (const float*)d_in[14];
    const float* lin1_b0 = (const float*)d_in[15];
    const float* lin1_w1 = (const float*)d_in[16];
    const float* lin2_w0 = (const float*)d_in[17];
    const float* lin2_b0 = (const float*)d_in[18];
    const float* lin2_w1 = (const float*)d_in[19];
    const float* lin3_w0 = (const float*)d_in[20];
    const float* lin3_b0 = (const float*)d_in[21];
    const float* lin3_w1 = (const float*)d_in[22];
    const float* tp_w    = (const float*)d_in[23];
    float* out = (float*)d_out;

    float *F0, *V, *H1, *H2, *G1, *G2, *VG1, *VG2, *SL, *SR, *VL, *VR,
          *F0t, *Vt, *H3, *G3, *VG3, *VO3;
    cudaGetSymbolAddress((void**)&F0,  g_F0);
    cudaGetSymbolAddress((void**)&V,   g_V);
    cudaGetSymbolAddress((void**)&H1,  g_H1);
    cudaGetSymbolAddress((void**)&H2,  g_H2);
    cudaGetSymbolAddress((void**)&G1,  g_G1);
    cudaGetSymbolAddress((void**)&G2,  g_G2);
    cudaGetSymbolAddress((void**)&VG1, g_VG1);
    cudaGetSymbolAddress((void**)&VG2, g_VG2);
    cudaGetSymbolAddress((void**)&SL,  g_SL);
    cudaGetSymbolAddress((void**)&SR,  g_SR);
    cudaGetSymbolAddress((void**)&VL,  g_VL);
    cudaGetSymbolAddress((void**)&VR,  g_VR);
    cudaGetSymbolAddress((void**)&F0t, g_F0t);
    cudaGetSymbolAddress((void**)&Vt,  g_Vt);
    cudaGetSymbolAddress((void**)&H3,  g_H3);
    cudaGetSymbolAddress((void**)&G3,  g_G3);
    cudaGetSymbolAddress((void**)&VG3, g_VG3);
    cudaGetSymbolAddress((void**)&VO3, g_VO3);

    const float inv16 = 0.0625f;  // 1/sqrt(256)

    // Stage 1: prep (shared by ng1 and ng2: same x)
    prep_kernel<<<NN, 256>>>(x, F0, V);

    // Stage 2: NormGate MLPs for left/right branches
    launch_gemm(F0, 512, ng1_w1, 512, H1, 512, ng1_b1, nullptr, 0, NN, 512, 512, 1.f, 1);
    launch_gemm(F0, 512, ng2_w1, 512, H2, 512, ng2_b1, nullptr, 0, NN, 512, 512, 1.f, 1);
    launch_gemm(H1, 512, ng1_w2, 512, G1, 512, ng1_b2, nullptr, 0, NN, 512, 512, 1.f, 0);
    launch_gemm(H2, 512, ng2_w2, 512, G2, 512, ng2_b2, nullptr, 0, NN, 512, 512, 1.f, 0);

    // Stage 3: gate vectors
    gate_kernel<<<NN * 3, 256>>>(V, G1, VG1);
    gate_kernel<<<NN * 3, 256>>>(V, G2, VG2);

    // Stage 4: irrep linears (scalar: gate scalars live in G[:, :256], lda=512)
    launch_gemm(G1, 512, lin1_w0, 256, SL, 256, lin1_b0, nullptr, 0, NN,     256, 256, inv16, 0);
    launch_gemm(VG1, 256, lin1_w1, 256, VL, 256, nullptr, nullptr, 0, 3 * NN, 256, 256, inv16, 0);
    launch_gemm(G2, 512, lin2_w0, 256, SR, 256, lin2_b0, nullptr, 0, NN,     256, 256, inv16, 0);
    launch_gemm(VG2, 256, lin2_w1, 256, VR, 256, nullptr, nullptr, 0, 3 * NN, 256, 256, inv16, 0);

    // Stage 5: tensor product + resnet(x) + norms for output gate
    tp_kernel<<<NN, 256>>>(SL, VL, SR, VR, F0, V, tp_w, F0t, Vt);

    // Stage 6: output NormGate
    launch_gemm(F0t, 512, ngo_w1, 512, H3, 512, ngo_b1, nullptr, 0, NN, 512, 512, 1.f, 1);
    launch_gemm(H3,  512, ngo_w2, 512, G3, 512, ngo_b2, nullptr, 0, NN, 512, 512, 1.f, 0);
    gate_kernel<<<NN * 3, 256>>>(Vt, G3, VG3);

    // Stage 7: final irrep linear + old_fii residual
    // scalars straight into out columns [0,256) with old_fii residual fused
    launch_gemm(G3, 512, lin3_w0, 256, out, 1024, lin3_b0, old_fii, 1024, NN, 256, 256, inv16, 0);
    // vectors to scratch, then interleave into out columns [256,1024)
    launch_gemm(VG3, 256, lin3_w1, 256, VO3, 256, nullptr, nullptr, 0, 3 * NN, 256, 256, inv16, 0);
    final_kernel<<<NN * 3, 256>>>(VO3, old_fii, out);
}

// round 12
// speedup vs baseline: 1.1179x; 1.1179x over previous
#include <cuda_runtime.h>
#include <cuda_bf16.h>
#include <mma.h>
#include <math.h>
#include <string.h>
#include <stdint.h>

using namespace nvcuda;

// Problem constants
#define NN   32768

// ---------------- scratch (allocation-free: __device__ globals) ----------------
__device__ float g_F0 [NN*512];
__device__ float g_V  [NN*768];
__device__ float g_H1 [NN*512];
__device__ float g_H2 [NN*512];
__device__ float g_G1 [NN*512];
__device__ float g_G2 [NN*512];
__device__ float g_VG1[NN*768];
__device__ float g_VG2[NN*768];
__device__ float g_SL [NN*256];
__device__ float g_SR [NN*256];
__device__ float g_VL [NN*768];
__device__ float g_VR [NN*768];
__device__ float g_F0t[NN*512];
__device__ float g_Vt [NN*768];
__device__ float g_H3 [NN*512];
__device__ float g_G3 [NN*512];
__device__ float g_VG3[NN*768];
__device__ float g_VO3[NN*768];

// ---------------- wmma split-bf16 GEMM, weights converted IN-KERNEL ----------
// C[M,Nc] = act( A[M,K](fp32) @ (alpha*W) + bias + res )
// W is the ORIGINAL fp32 [K, Nc] row-major harness input.
// SMEM tiles (bf16, padded leading dim LDE=40 elements = 80 B):
//   AH [128][40]  row-major   (A hi)        offset     0 elements
//   AL [128][40]  row-major   (A lo)        offset  5120
//   BH [128][40]  n-major rows, k contiguous = col-major k x n (B hi)  offset 10240
//   BL [128][40]                                  (B lo)               offset 15360
// Total 20480 bf16 = 40960 B static SMEM (< 48 KB, no opt-in).
// grid = (Nc/128, M/128), 256 threads = 8 warps in 2(m) x 4(n); warp tile 64x32.
#define LDE 40

__global__ void __launch_bounds__(256)
gemm_tc(const float* __restrict__ A, int lda,
        const float* __restrict__ Wf, int ldb,
        float* __restrict__ C, int ldc,
        const float* __restrict__ bias,
        const float* __restrict__ res, int ldres,
        int K, float alpha, int act)
{
    __shared__ __align__(32) __nv_bfloat16 sm[20480];
    __nv_bfloat16* AH = sm;
    __nv_bfloat16* AL = sm + 5120;
    __nv_bfloat16* BH = sm + 10240;
    __nv_bfloat16* BL = sm + 15360;

    const int tid  = threadIdx.x;
    const int wid  = tid >> 5;
    const int wm   = wid & 1;    // 0..1 : 64 rows each
    const int wn   = wid >> 1;   // 0..3 : 32 cols each
    const int block_m = blockIdx.y * 128;
    const int block_n = blockIdx.x * 128;

    wmma::fragment<wmma::accumulator, 16, 16, 16, float> acc[4][2];
#pragma unroll
    for (int mi = 0; mi < 4; ++mi)
#pragma unroll
        for (int ni = 0; ni < 2; ++ni)
            wmma::fill_fragment(acc[mi][ni], 0.0f);

    float4 aR[4];      // A prefetch: 128 rows x 32 k
    float  wB[4][4];   // W prefetch: 128 n x 32 k (4 ids x 4 q)

    const int nk = K >> 5;

    // ---- prefetch + store helpers (lambdas keep indices in one place) ----
    auto LDG = [&](int k0) {
#pragma unroll
        for (int it = 0; it < 4; ++it) {
            int id = it * 256 + tid, row = id >> 3, c4 = id & 7;
            aR[it] = *reinterpret_cast<const float4*>(
                A + (size_t)(block_m + row) * lda + k0 + c4 * 4);
        }
#pragma unroll
        for (int it = 0; it < 4; ++it) {
            int id = it * 256 + tid, nrow = id >> 3, c4 = id & 7;
#pragma unroll
            for (int q = 0; q < 4; ++q)
                wB[it][q] = Wf[(size_t)(k0 + c4 * 4 + q) * ldb + block_n + nrow];
        }
    };
    auto STS = [&]() {
#pragma unroll
        for (int it = 0; it < 4; ++it) {
            int id = it * 256 + tid, row = id >> 3, c4 = id & 7;
            float av[4] = {aR[it].x, aR[it].y, aR[it].z, aR[it].w};
#pragma unroll
            for (int q = 0; q < 4; ++q) {
                float v = av[q];
                __nv_bfloat16 h = __float2bfloat16(v);
                __nv_bfloat16 l = __float2bfloat16(v - __bfloat162float(h));
                AH[row * LDE + c4 * 4 + q] = h;
                AL[row * LDE + c4 * 4 + q] = l;
            }
        }
#pragma unroll
        for (int it = 0; it < 4; ++it) {
            int id = it * 256 + tid, nrow = id >> 3, c4 = id & 7;
#pragma unroll
            for (int q = 0; q < 4; ++q) {
                float v = wB[it][q] * alpha;
                __nv_bfloat16 h = __float2bfloat16(v);
                __nv_bfloat16 l = __float2bfloat16(v - __bfloat162float(h));
                BH[nrow * LDE + c4 * 4 + q] = h;
                BL[nrow * LDE + c4 * 4 + q] = l;
            }
        }
    };

    LDG(0);
    STS();
    __syncthreads();

    for (int it = 0; it < nk; ++it) {
        if (it + 1 < nk) LDG((it + 1) << 5);   // prefetch next tile into registers

        // compute on current SMEM tile: BK=32 = 2 wmma k-steps
#pragma unroll
        for (int ks = 0; ks < 2; ++ks) {
            const int kofs = ks * 16;
            wmma::fragment<wmma::matrix_a, 16, 16, 16, __nv_bfloat16, wmma::row_major> fah[4], fal[4];
#pragma unroll
            for (int mi = 0; mi < 4; ++mi) {
                wmma::load_matrix_sync(fah[mi], AH + (wm * 64 + mi * 16) * LDE + kofs, LDE);
                wmma::load_matrix_sync(fal[mi], AL + (wm * 64 + mi * 16) * LDE + kofs, LDE);
            }
#pragma unroll
            for (int ni = 0; ni < 2; ++ni) {
                wmma::fragment<wmma::matrix_b, 16, 16, 16, __nv_bfloat16, wmma::col_major> fbh, fbl;
                wmma::load_matrix_sync(fbh, BH + (wn * 32 + ni * 16) * LDE + kofs, LDE);
                wmma::load_matrix_sync(fbl, BL + (wn * 32 + ni * 16) * LDE + kofs, LDE);
#pragma unroll
                for (int mi = 0; mi < 4; ++mi) {
                    wmma::mma_sync(acc[mi][ni], fah[mi], fbh, acc[mi][ni]);
                    wmma::mma_sync(acc[mi][ni], fah[mi], fbl, acc[mi][ni]);
                    wmma::mma_sync(acc[mi][ni], fal[mi], fbh, acc[mi][ni]);
                }
            }
        }
        __syncthreads();                 // all warps done reading SMEM
        if (it + 1 < nk) {
            STS();
            __syncthreads();             // SMEM ready for next compute
        }
    }

    // ---- epilogue: two half-tile passes through SMEM (64 x 128 f32 = 32 KB) ----
    float* sf = reinterpret_cast<float*>(sm);
#pragma unroll
    for (int pass = 0; pass < 2; ++pass) {
        if (wm == pass) {
#pragma unroll
            for (int mi = 0; mi < 4; ++mi)
#pragma unroll
                for (int ni = 0; ni < 2; ++ni)
                    wmma::store_matrix_sync(sf + (mi * 16) * 128 + wn * 32 + ni * 16,
                                            acc[mi][ni], 128, wmma::mem_row_major);
        }
        __syncthreads();
        for (int i = tid; i < 2048; i += 256) {   // 64 rows x 32 float4
            int r = i >> 5, c4 = (i & 31) * 4;
            float4 v = *reinterpret_cast<float4*>(sf + r * 128 + c4);
            int row = block_m + pass * 64 + r;
            int col = block_n + c4;
            float vv[4] = {v.x, v.y, v.z, v.w};
#pragma unroll
            for (int j = 0; j < 4; ++j) {
                float t = vv[j];
                if (bias) t += bias[col + j];
                if (res)  t += res[(size_t)row * ldres + col + j];
                if (act)  t = t / (1.0f + __expf(-t));
                vv[j] = t;
            }
            float4 o; o.x = vv[0]; o.y = vv[1]; o.z = vv[2]; o.w = vv[3];
            *reinterpret_cast<float4*>(C + (size_t)row * ldc + col) = o;
        }
        __syncthreads();
    }
}

// ---------------- elementwise kernels (verified in R3) ----------------
__global__ void prep_kernel(const float* __restrict__ x,
                            float* __restrict__ F0, float* __restrict__ V)
{
    const int n = blockIdx.x;
    const int u = threadIdx.x;
    const float* xr = x + (size_t)n * 1024;
    float s  = xr[u];
    float v0 = xr[256 + 3 * u + 0];
    float v1 = xr[256 + 3 * u + 1];
    float v2 = xr[256 + 3 * u + 2];
    F0[(size_t)n * 512 + u]       = s;
    F0[(size_t)n * 512 + 256 + u] = sqrtf(v0 * v0 + v1 * v1 + v2 * v2 + 1e-12f);
    size_t vb = ((size_t)3 * n) * 256 + u;
    V[vb]       = v0;
    V[vb + 256] = v1;
    V[vb + 512] = v2;
}

__global__ void gate_kernel(const float* __restrict__ V,
                            const float* __restrict__ G,
                            float* __restrict__ VG)
{
    size_t idx = (size_t)blockIdx.x * blockDim.x + threadIdx.x;
    int u = (int)(idx & 255);
    size_t r = idx >> 8;
    size_t n = r / 3;
    VG[idx] = V[idx] * G[n * 512 + 256 + u];
}

__global__ void tp_kernel(const float* __restrict__ SL, const float* __restrict__ VL,
                          const float* __restrict__ SR, const float* __restrict__ VR,
                          const float* __restrict__ F0, const float* __restrict__ V,
                          const float* __restrict__ tpw,
                          float* __restrict__ F0t, float* __restrict__ Vt)
{
    const int n = blockIdx.x;
    const int u = threadIdx.x;
    const size_t b256 = (size_t)n * 256 + u;
    const size_t b512 = (size_t)n * 512 + u;
    const size_t vb   = ((size_t)3 * n) * 256 + u;

    float s1 = SL[b256], s2 = SR[b256];
    float ax = VL[vb], ay = VL[vb + 256], az = VL[vb + 512];
    float bx = VR[vb], by = VR[vb + 256], bz = VR[vb + 512];
    float w0 = tpw[u], w1 = tpw[256 + u], w2 = tpw[512 + u],
          w3 = tpw[768 + u], w4 = tpw[1024 + u];

    const float A0 = 0.44721359549995793f;
    const float A1 = 0.77459666924148340f;
    const float I3 = 0.57735026918962576f;
    const float I6 = 0.40824829046386302f;

    float dot = ax * bx + ay * by + az * bz;
    float t0 = A0 * (w0 * s1 * s2 + w3 * I3 * dot) + F0[b512];

    float cx = ay * bz - az * by;
    float cy = az * bx - ax * bz;
    float cz = ax * by - ay * bx;
    float k1 = A1 * I3 * w1 * s1;
    float k2 = A1 * I3 * w2 * s2;
    float k4 = A1 * I6 * w4;
    float tx = k1 * bx + k2 * ax + k4 * cx + V[vb];
    float ty = k1 * by + k2 * ay + k4 * cy + V[vb + 256];
    float tz = k1 * bz + k2 * az + k4 * cz + V[vb + 512];

    F0t[b512]       = t0;
    F0t[b512 + 256] = sqrtf(tx * tx + ty * ty + tz * tz + 1e-12f);
    Vt[vb]       = tx;
    Vt[vb + 256] = ty;
    Vt[vb + 512] = tz;
}

__global__ void final_kernel(const float* __restrict__ VO3,
                             const float* __restrict__ old_fii,
                             float* __restrict__ out)
{
    size_t idx = (size_t)blockIdx.x * blockDim.x + threadIdx.x;
    size_t n = idx / 768;
    int j = (int)(idx % 768);
    int u = j / 3;
    int i = j % 3;
    size_t o = n * 1024 + 256 + j;
    out[o] = old_fii[o] + VO3[((size_t)3 * n + i) * 256 + u];
}

// ---------------- host launch ----------------
static inline void launch_tc(const float* A, int lda,
                             const float* Wf, int ldb,
                             float* C, int ldc, const float* bias,
                             const float* res, int ldres,
                             int M, int Nc, int K, float alpha, int act)
{
    dim3 grid(Nc / 128, M / 128);
    gemm_tc<<<grid, 256>>>(A, lda, Wf, ldb, C, ldc, bias, res, ldres, K, alpha, act);
}

extern "C" void kernel_launch(void* const* d_in, const int* in_sizes, int n_in,
                              void* d_out, int out_size)
{
    const float* x       = (const float*)d_in[0];
    const float* old_fii = (const float*)d_in[1];
    const float* ng1_w1 = (const float*)d_in[2];
    const float* ng1_b1 = (const float*)d_in[3];
    const float* ng1_w2 = (const float*)d_in[4];
    const float* ng1_b2 = (const float*)d_in[5];
    const float* ng2_w1 = (const float*)d_in[6];
    const float* ng2_b1 = (const float*)d_in[7];
    const float* ng2_w2 = (const float*)d_in[8];
    const float* ng2_b2 = (const float*)d_in[9];
    const float* ngo_w1 = (const float*)d_in[10];
    const float* ngo_b1 = (const float*)d_in[11];
    const float* ngo_w2 = (const float*)d_in[12];
    const float* ngo_b2 = (const float*)d_in[13];
    const float* lin1_w0 = (const float*)d_in[14];
    const float* lin1_b0 = (const float*)d_in[15];
    const float* lin1_w1 = (const float*)d_in[16];
    const float* lin2_w0 = (const float*)d_in[17];
    const float* lin2_b0 = (const float*)d_in[18];
    const float* lin2_w1 = (const float*)d_in[19];
    const float* lin3_w0 = (const float*)d_in[20];
    const float* lin3_b0 = (const float*)d_in[21];
    const float* lin3_w1 = (const float*)d_in[22];
    const float* tp_w    = (const float*)d_in[23];
    float* out = (float*)d_out;

    float *F0, *V, *H1, *H2, *G1, *G2, *VG1, *VG2, *SL, *SR, *VL, *VR,
          *F0t, *Vt, *H3, *G3, *VG3, *VO3;
    cudaGetSymbolAddress((void**)&F0,  g_F0);
    cudaGetSymbolAddress((void**)&V,   g_V);
    cudaGetSymbolAddress((void**)&H1,  g_H1);
    cudaGetSymbolAddress((void**)&H2,  g_H2);
    cudaGetSymbolAddress((void**)&G1,  g_G1);
    cudaGetSymbolAddress((void**)&G2,  g_G2);
    cudaGetSymbolAddress((void**)&VG1, g_VG1);
    cudaGetSymbolAddress((void**)&VG2, g_VG2);
    cudaGetSymbolAddress((void**)&SL,  g_SL);
    cudaGetSymbolAddress((void**)&SR,  g_SR);
    cudaGetSymbolAddress((void**)&VL,  g_VL);
    cudaGetSymbolAddress((void**)&VR,  g_VR);
    cudaGetSymbolAddress((void**)&F0t, g_F0t);
    cudaGetSymbolAddress((void**)&Vt,  g_Vt);
    cudaGetSymbolAddress((void**)&H3,  g_H3);
    cudaGetSymbolAddress((void**)&G3,  g_G3);
    cudaGetSymbolAddress((void**)&VG3, g_VG3);
    cudaGetSymbolAddress((void**)&VO3, g_VO3);

    const float inv16 = 0.0625f;  // 1/sqrt(256), applied to lin weights in-kernel

    // Stage 1: prep
    prep_kernel<<<NN, 256>>>(x, F0, V);

    // Stage 2: NormGate MLPs (left/right)
    launch_tc(F0, 512, ng1_w1, 512, H1, 512, ng1_b1, nullptr, 0, NN, 512, 512, 1.f, 1);
    launch_tc(F0, 512, ng2_w1, 512, H2, 512, ng2_b1, nullptr, 0, NN, 512, 512, 1.f, 1);
    launch_tc(H1, 512, ng1_w2, 512, G1, 512, ng1_b2, nullptr, 0, NN, 512, 512, 1.f, 0);
    launch_tc(H2, 512, ng2_w2, 512, G2, 512, ng2_b2, nullptr, 0, NN, 512, 512, 1.f, 0);

    // Stage 3: gate vectors
    gate_kernel<<<NN * 3, 256>>>(V, G1, VG1);
    gate_kernel<<<NN * 3, 256>>>(V, G2, VG2);

    // Stage 4: irrep linears
    launch_tc(G1,  512, lin1_w0, 256, SL, 256, lin1_b0, nullptr, 0, NN,     256, 256, inv16, 0);
    launch_tc(VG1, 256, lin1_w1, 256, VL, 256, nullptr, nullptr, 0, 3 * NN, 256, 256, inv16, 0);
    launch_tc(G2,  512, lin2_w0, 256, SR, 256, lin2_b0, nullptr, 0, NN,     256, 256, inv16, 0);
    launch_tc(VG2, 256, lin2_w1, 256, VR, 256, nullptr, nullptr, 0, 3 * NN, 256, 256, inv16, 0);

    // Stage 5: tensor product + resnet
    tp_kernel<<<NN, 256>>>(SL, VL, SR, VR, F0, V, tp_w, F0t, Vt);

    // Stage 6: output NormGate
    launch_tc(F0t, 512, ngo_w1, 512, H3, 512, ngo_b1, nullptr, 0, NN, 512, 512, 1.f, 1);
    launch_tc(H3,  512, ngo_w2, 512, G3, 512, ngo_b2, nullptr, 0, NN, 512, 512, 1.f, 0);
    gate_kernel<<<NN * 3, 256>>>(Vt, G3, VG3);

    // Stage 7: final irrep linear + old_fii residual
    launch_tc(G3,  512, lin3_w0, 256, out, 1024, lin3_b0, old_fii, 1024, NN, 256, 256, inv16, 0);
    launch_tc(VG3, 256, lin3_w1, 256, VO3, 256, nullptr, nullptr, 0, 3 * NN, 256, 256, inv16, 0);
    final_kernel<<<NN * 3, 256>>>(VO3, old_fii, out);
}

// round 13
// speedup vs baseline: 1.3267x; 1.1868x over previous
#include <cuda_runtime.h>
#include <cuda_bf16.h>
#include <mma.h>
#include <math.h>
#include <string.h>
#include <stdint.h>

using namespace nvcuda;

// Problem constants
#define NN   32768

// ---------------- scratch (allocation-free: __device__ globals) ----------------
__device__ float g_F0 [NN*512];
__device__ float g_V  [NN*768];
__device__ float g_H1 [NN*512];
__device__ float g_H2 [NN*512];
__device__ float g_G1 [NN*512];
__device__ float g_G2 [NN*512];
__device__ float g_VG1[NN*768];
__device__ float g_VG2[NN*768];
__device__ float g_SL [NN*256];
__device__ float g_SR [NN*256];
__device__ float g_VL [NN*768];
__device__ float g_VR [NN*768];
__device__ float g_F0t[NN*512];
__device__ float g_Vt [NN*768];
__device__ float g_H3 [NN*512];
__device__ float g_G3 [NN*512];
__device__ float g_VG3[NN*768];
__device__ float g_VO3[NN*768];

// converted weights: [Nc][K] bf16 (n-major rows, k contiguous), alpha folded in
#define WTOTAL 1966080
__device__ __nv_bfloat16 g_Whi[WTOTAL];
__device__ __nv_bfloat16 g_Wlo[WTOTAL];

// ---------------- wmma split-bf16 GEMM, double-buffered ----------------------
// C[M,Nc] = act( A[M,K](fp32) @ Wt^T + bias + res ), Wt = [Nc][K] bf16 hi/lo
// SMEM per stage (bf16, padded leading dim LDE=40 elements = 80 B):
//   AH [128][40] row-major, AL, BH [128][40] n-rows/k-contig (col-major KxN), BL
// stage size 20480 bf16 = 40960 B; 2 stages = 81920 B dynamic (opt-in).
// grid = (Nc/128, M/128), 256 threads = 8 warps in 2(m) x 4(n); warp tile 64x32.
#define LDE 40
#define STAGE_E 20480
#define GEMM_SMEM 81920

__global__ void __launch_bounds__(256)
gemm_tc(const float* __restrict__ A, int lda,
        const __nv_bfloat16* __restrict__ Bhi,
        const __nv_bfloat16* __restrict__ Blo,
        float* __restrict__ C, int ldc,
        const float* __restrict__ bias,
        const float* __restrict__ res, int ldres,
        int K, int act)
{
    extern __shared__ __align__(16) __nv_bfloat16 smx[];

    const int tid  = threadIdx.x;
    const int wid  = tid >> 5;
    const int wm   = wid & 1;    // 0..1 : 64 rows each
    const int wn   = wid >> 1;   // 0..3 : 32 cols each
    const int block_m = blockIdx.y * 128;
    const int block_n = blockIdx.x * 128;

    wmma::fragment<wmma::accumulator, 16, 16, 16, float> acc[4][2];
#pragma unroll
    for (int mi = 0; mi < 4; ++mi)
#pragma unroll
        for (int ni = 0; ni < 2; ++ni)
            wmma::fill_fragment(acc[mi][ni], 0.0f);

    float4 aR[4];           // A prefetch: 128 rows x 32 k fp32
    uint4  bhR[2], blR[2];  // W prefetch: 128 n-rows x 32 k bf16 (hi/lo)

    const int nk = K >> 5;

    auto LDG = [&](int k0) {
#pragma unroll
        for (int it = 0; it < 4; ++it) {
            int id = it * 256 + tid, row = id >> 3, c4 = id & 7;
            aR[it] = *reinterpret_cast<const float4*>(
                A + (size_t)(block_m + row) * lda + k0 + c4 * 4);
        }
#pragma unroll
        for (int it = 0; it < 2; ++it) {
            int id = it * 256 + tid, nrow = id >> 2, c = id & 3;  // c*8 bf16
            size_t off = (size_t)(block_n + nrow) * K + k0 + c * 8;
            bhR[it] = *reinterpret_cast<const uint4*>(Bhi + off);
            blR[it] = *reinterpret_cast<const uint4*>(Blo + off);
        }
    };
    auto STS = [&](int s) {
        __nv_bfloat16* AH = smx + s * STAGE_E;
        __nv_bfloat16* AL = AH + 5120;
        __nv_bfloat16* BH = AH + 10240;
        __nv_bfloat16* BL = AH + 15360;
#pragma unroll
        for (int it = 0; it < 4; ++it) {
            int id = it * 256 + tid, row = id >> 3, c4 = id & 7;
            float av[4] = {aR[it].x, aR[it].y, aR[it].z, aR[it].w};
#pragma unroll
            for (int q = 0; q < 4; ++q) {
                float v = av[q];
                __nv_bfloat16 h = __float2bfloat16(v);
                __nv_bfloat16 l = __float2bfloat16(v - __bfloat162float(h));
                AH[row * LDE + c4 * 4 + q] = h;
                AL[row * LDE + c4 * 4 + q] = l;
            }
        }
#pragma unroll
        for (int it = 0; it < 2; ++it) {
            int id = it * 256 + tid, nrow = id >> 2, c = id & 3;
            *reinterpret_cast<uint4*>(BH + nrow * LDE + c * 8) = bhR[it];
            *reinterpret_cast<uint4*>(BL + nrow * LDE + c * 8) = blR[it];
        }
    };
    auto COMPUTE = [&](int s) {
        const __nv_bfloat16* AH = smx + s * STAGE_E;
        const __nv_bfloat16* AL = AH + 5120;
        const __nv_bfloat16* BH = AH + 10240;
        const __nv_bfloat16* BL = AH + 15360;
#pragma unroll
        for (int ks = 0; ks < 2; ++ks) {
            const int kofs = ks * 16;
            wmma::fragment<wmma::matrix_a, 16, 16, 16, __nv_bfloat16, wmma::row_major> fah[4], fal[4];
#pragma unroll
            for (int mi = 0; mi < 4; ++mi) {
                wmma::load_matrix_sync(fah[mi], AH + (wm * 64 + mi * 16) * LDE + kofs, LDE);
                wmma::load_matrix_sync(fal[mi], AL + (wm * 64 + mi * 16) * LDE + kofs, LDE);
            }
#pragma unroll
            for (int ni = 0; ni < 2; ++ni) {
                wmma::fragment<wmma::matrix_b, 16, 16, 16, __nv_bfloat16, wmma::col_major> fbh, fbl;
                wmma::load_matrix_sync(fbh, BH + (wn * 32 + ni * 16) * LDE + kofs, LDE);
                wmma::load_matrix_sync(fbl, BL + (wn * 32 + ni * 16) * LDE + kofs, LDE);
#pragma unroll
                for (int mi = 0; mi < 4; ++mi) {
                    wmma::mma_sync(acc[mi][ni], fah[mi], fbh, acc[mi][ni]);
                    wmma::mma_sync(acc[mi][ni], fah[mi], fbl, acc[mi][ni]);
                    wmma::mma_sync(acc[mi][ni], fal[mi], fbh, acc[mi][ni]);
                }
            }
        }
    };

    LDG(0);
    STS(0);
    __syncthreads();

    for (int it = 0; it < nk; ++it) {
        if (it + 1 < nk) LDG((it + 1) << 5);   // prefetch next tile into regs
        COMPUTE(it & 1);                        // read current stage
        if (it + 1 < nk) STS((it + 1) & 1);     // write OTHER stage
        __syncthreads();                        // one sync per iteration
    }

    // ---- epilogue: two half-tile passes through SMEM (64 x 128 f32 = 32 KB) ----
    float* sf = reinterpret_cast<float*>(smx);
    __syncthreads();
#pragma unroll
    for (int pass = 0; pass < 2; ++pass) {
        if (wm == pass) {
#pragma unroll
            for (int mi = 0; mi < 4; ++mi)
#pragma unroll
                for (int ni = 0; ni < 2; ++ni)
                    wmma::store_matrix_sync(sf + (mi * 16) * 128 + wn * 32 + ni * 16,
                                            acc[mi][ni], 128, wmma::mem_row_major);
        }
        __syncthreads();
        for (int i = tid; i < 2048; i += 256) {   // 64 rows x 32 float4
            int r = i >> 5, c4 = (i & 31) * 4;
            float4 v = *reinterpret_cast<float4*>(sf + r * 128 + c4);
            int row = block_m + pass * 64 + r;
            int col = block_n + c4;
            float vv[4] = {v.x, v.y, v.z, v.w};
#pragma unroll
            for (int j = 0; j < 4; ++j) {
                float t = vv[j];
                if (bias) t += bias[col + j];
                if (res)  t += res[(size_t)row * ldres + col + j];
                if (act)  t = t / (1.0f + __expf(-t));
                vv[j] = t;
            }
            float4 o; o.x = vv[0]; o.y = vv[1]; o.z = vv[2]; o.w = vv[3];
            *reinterpret_cast<float4*>(C + (size_t)row * ldc + col) = o;
        }
        __syncthreads();
    }
}

// ---------------- weight conversion: W[K,Nc] fp32 -> Wt[Nc][K] bf16 hi/lo ----
__global__ void convert_w(const float* __restrict__ W,
                          __nv_bfloat16* __restrict__ hi,
                          __nv_bfloat16* __restrict__ lo,
                          int K, int Nc, float scale)
{
    int idx = blockIdx.x * blockDim.x + threadIdx.x;
    if (idx >= K * Nc) return;
    int n = idx / K, k = idx % K;
    float v = W[(size_t)k * Nc + n] * scale;
    __nv_bfloat16 h = __float2bfloat16(v);
    float rlo = v - __bfloat162float(h);
    hi[idx] = h;
    lo[idx] = __float2bfloat16(rlo);
}

// ---------------- elementwise kernels (verified) ----------------
__global__ void prep_kernel(const float* __restrict__ x,
                            float* __restrict__ F0, float* __restrict__ V)
{
    const int n = blockIdx.x;
    const int u = threadIdx.x;
    const float* xr = x + (size_t)n * 1024;
    float s  = xr[u];
    float v0 = xr[256 + 3 * u + 0];
    float v1 = xr[256 + 3 * u + 1];
    float v2 = xr[256 + 3 * u + 2];
    F0[(size_t)n * 512 + u]       = s;
    F0[(size_t)n * 512 + 256 + u] = sqrtf(v0 * v0 + v1 * v1 + v2 * v2 + 1e-12f);
    size_t vb = ((size_t)3 * n) * 256 + u;
    V[vb]       = v0;
    V[vb + 256] = v1;
    V[vb + 512] = v2;
}

__global__ void gate_kernel(const float* __restrict__ V,
                            const float* __restrict__ G,
                            float* __restrict__ VG)
{
    size_t idx = (size_t)blockIdx.x * blockDim.x + threadIdx.x;
    int u = (int)(idx & 255);
    size_t r = idx >> 8;
    size_t n = r / 3;
    VG[idx] = V[idx] * G[n * 512 + 256 + u];
}

__global__ void tp_kernel(const float* __restrict__ SL, const float* __restrict__ VL,
                          const float* __restrict__ SR, const float* __restrict__ VR,
                          const float* __restrict__ F0, const float* __restrict__ V,
                          const float* __restrict__ tpw,
                          float* __restrict__ F0t, float* __restrict__ Vt)
{
    const int n = blockIdx.x;
    const int u = threadIdx.x;
    const size_t b256 = (size_t)n * 256 + u;
    const size_t b512 = (size_t)n * 512 + u;
    const size_t vb   = ((size_t)3 * n) * 256 + u;

    float s1 = SL[b256], s2 = SR[b256];
    float ax = VL[vb], ay = VL[vb + 256], az = VL[vb + 512];
    float bx = VR[vb], by = VR[vb + 256], bz = VR[vb + 512];
    float w0 = tpw[u], w1 = tpw[256 + u], w2 = tpw[512 + u],
          w3 = tpw[768 + u], w4 = tpw[1024 + u];

    const float A0 = 0.44721359549995793f;
    const float A1 = 0.77459666924148340f;
    const float I3 = 0.57735026918962576f;
    const float I6 = 0.40824829046386302f;

    float dot = ax * bx + ay * by + az * bz;
    float t0 = A0 * (w0 * s1 * s2 + w3 * I3 * dot) + F0[b512];

    float cx = ay * bz - az * by;
    float cy = az * bx - ax * bz;
    float cz = ax * by - ay * bx;
    float k1 = A1 * I3 * w1 * s1;
    float k2 = A1 * I3 * w2 * s2;
    float k4 = A1 * I6 * w4;
    float tx = k1 * bx + k2 * ax + k4 * cx + V[vb];
    float ty = k1 * by + k2 * ay + k4 * cy + V[vb + 256];
    float tz = k1 * bz + k2 * az + k4 * cz + V[vb + 512];

    F0t[b512]       = t0;
    F0t[b512 + 256] = sqrtf(tx * tx + ty * ty + tz * tz + 1e-12f);
    Vt[vb]       = tx;
    Vt[vb + 256] = ty;
    Vt[vb + 512] = tz;
}

__global__ void final_kernel(const float* __restrict__ VO3,
                             const float* __restrict__ old_fii,
                             float* __restrict__ out)
{
    size_t idx = (size_t)blockIdx.x * blockDim.x + threadIdx.x;
    size_t n = idx / 768;
    int j = (int)(idx % 768);
    int u = j / 3;
    int i = j % 3;
    size_t o = n * 1024 + 256 + j;
    out[o] = old_fii[o] + VO3[((size_t)3 * n + i) * 256 + u];
}

// ---------------- host launch ----------------
static inline void launch_tc(const float* A, int lda,
                             const __nv_bfloat16* bh, const __nv_bfloat16* bl,
                             float* C, int ldc, const float* bias,
                             const float* res, int ldres,
                             int M, int Nc, int K, int act)
{
    dim3 grid(Nc / 128, M / 128);
    gemm_tc<<<grid, 256, GEMM_SMEM>>>(A, lda, bh, bl, C, ldc, bias, res, ldres, K, act);
}

extern "C" void kernel_launch(void* const* d_in, const int* in_sizes, int n_in,
                              void* d_out, int out_size)
{
    const float* x       = (const float*)d_in[0];
    const float* old_fii = (const float*)d_in[1];
    const float* ng1_w1 = (const float*)d_in[2];
    const float* ng1_b1 = (const float*)d_in[3];
    const float* ng1_w2 = (const float*)d_in[4];
    const float* ng1_b2 = (const float*)d_in[5];
    const float* ng2_w1 = (const float*)d_in[6];
    const float* ng2_b1 = (const float*)d_in[7];
    const float* ng2_w2 = (const float*)d_in[8];
    const float* ng2_b2 = (const float*)d_in[9];
    const float* ngo_w1 = (const float*)d_in[10];
    const float* ngo_b1 = (const float*)d_in[11];
    const float* ngo_w2 = (const float*)d_in[12];
    const float* ngo_b2 = (const float*)d_in[13];
    const float* lin1_w0 = (const float*)d_in[14];
    const float* lin1_b0 = (const float*)d_in[15];
    const float* lin1_w1 = (const float*)d_in[16];
    const float* lin2_w0 = (const float*)d_in[17];
    const float* lin2_b0 = (const float*)d_in[18];
    const float* lin2_w1 = (const float*)d_in[19];
    const float* lin3_w0 = (const float*)d_in[20];
    const float* lin3_b0 = (const float*)d_in[21];
    const float* lin3_w1 = (const float*)d_in[22];
    const float* tp_w    = (const float*)d_in[23];
    float* out = (float*)d_out;

    cudaFuncSetAttribute(gemm_tc, cudaFuncAttributeMaxDynamicSharedMemorySize, GEMM_SMEM);

    float *F0, *V, *H1, *H2, *G1, *G2, *VG1, *VG2, *SL, *SR, *VL, *VR,
          *F0t, *Vt, *H3, *G3, *VG3, *VO3;
    __nv_bfloat16 *Whi, *Wlo;
    cudaGetSymbolAddress((void**)&F0,  g_F0);
    cudaGetSymbolAddress((void**)&V,   g_V);
    cudaGetSymbolAddress((void**)&H1,  g_H1);
    cudaGetSymbolAddress((void**)&H2,  g_H2);
    cudaGetSymbolAddress((void**)&G1,  g_G1);
    cudaGetSymbolAddress((void**)&G2,  g_G2);
    cudaGetSymbolAddress((void**)&VG1, g_VG1);
    cudaGetSymbolAddress((void**)&VG2, g_VG2);
    cudaGetSymbolAddress((void**)&SL,  g_SL);
    cudaGetSymbolAddress((void**)&SR,  g_SR);
    cudaGetSymbolAddress((void**)&VL,  g_VL);
    cudaGetSymbolAddress((void**)&VR,  g_VR);
    cudaGetSymbolAddress((void**)&F0t, g_F0t);
    cudaGetSymbolAddress((void**)&Vt,  g_Vt);
    cudaGetSymbolAddress((void**)&H3,  g_H3);
    cudaGetSymbolAddress((void**)&G3,  g_G3);
    cudaGetSymbolAddress((void**)&VG3, g_VG3);
    cudaGetSymbolAddress((void**)&VO3, g_VO3);
    cudaGetSymbolAddress((void**)&Whi, g_Whi);
    cudaGetSymbolAddress((void**)&Wlo, g_Wlo);

    // weight scratch offsets (elements)
    const int OB = 262144;  // 512*512
    const int OS = 65536;   // 256*256
    const int o_ng1w1 = 0,        o_ng2w1 = OB,       o_ng1w2 = 2*OB,
              o_ng2w2 = 3*OB,     o_ngow1 = 4*OB,     o_ngow2 = 5*OB;
    const int o_l1w0 = 6*OB,          o_l1w1 = 6*OB + OS,   o_l2w0 = 6*OB + 2*OS,
              o_l2w1 = 6*OB + 3*OS,   o_l3w0 = 6*OB + 4*OS, o_l3w1 = 6*OB + 5*OS;

    const float inv16 = 0.0625f;  // 1/sqrt(256), folded into lin weights

    // ---- convert weights once (transpose to [Nc][K], bf16 hi/lo split) ----
    {
        const int T = 256;
        const int nb5 = (512*512 + T - 1) / T;
        const int ns5 = (256*256 + T - 1) / T;
        convert_w<<<nb5, T>>>(ng1_w1, Whi + o_ng1w1, Wlo + o_ng1w1, 512, 512, 1.f);
        convert_w<<<nb5, T>>>(ng2_w1, Whi + o_ng2w1, Wlo + o_ng2w1, 512, 512, 1.f);
        convert_w<<<nb5, T>>>(ng1_w2, Whi + o_ng1w2, Wlo + o_ng1w2, 512, 512, 1.f);
        convert_w<<<nb5, T>>>(ng2_w2, Whi + o_ng2w2, Wlo + o_ng2w2, 512, 512, 1.f);
        convert_w<<<nb5, T>>>(ngo_w1, Whi + o_ngow1, Wlo + o_ngow1, 512, 512, 1.f);
        convert_w<<<nb5, T>>>(ngo_w2, Whi + o_ngow2, Wlo + o_ngow2, 512, 512, 1.f);
        convert_w<<<ns5, T>>>(lin1_w0, Whi + o_l1w0, Wlo + o_l1w0, 256, 256, inv16);
        convert_w<<<ns5, T>>>(lin1_w1, Whi + o_l1w1, Wlo + o_l1w1, 256, 256, inv16);
        convert_w<<<ns5, T>>>(lin2_w0, Whi + o_l2w0, Wlo + o_l2w0, 256, 256, inv16);
        convert_w<<<ns5, T>>>(lin2_w1, Whi + o_l2w1, Wlo + o_l2w1, 256, 256, inv16);
        convert_w<<<ns5, T>>>(lin3_w0, Whi + o_l3w0, Wlo + o_l3w0, 256, 256, inv16);
        convert_w<<<ns5, T>>>(lin3_w1, Whi + o_l3w1, Wlo + o_l3w1, 256, 256, inv16);
    }

    // Stage 1: prep
    prep_kernel<<<NN, 256>>>(x, F0, V);

    // Stage 2: NormGate MLPs (left/right)
    launch_tc(F0, 512, Whi + o_ng1w1, Wlo + o_ng1w1, H1, 512, ng1_b1, nullptr, 0, NN, 512, 512, 1);
    launch_tc(F0, 512, Whi + o_ng2w1, Wlo + o_ng2w1, H2, 512, ng2_b1, nullptr, 0, NN, 512, 512, 1);
    launch_tc(H1, 512, Whi + o_ng1w2, Wlo + o_ng1w2, G1, 512, ng1_b2, nullptr, 0, NN, 512, 512, 0);
    launch_tc(H2, 512, Whi + o_ng2w2, Wlo + o_ng2w2, G2, 512, ng2_b2, nullptr, 0, NN, 512, 512, 0);

    // Stage 3: gate vectors
    gate_kernel<<<NN * 3, 256>>>(V, G1, VG1);
    gate_kernel<<<NN * 3, 256>>>(V, G2, VG2);

    // Stage 4: irrep linears
    launch_tc(G1,  512, Whi + o_l1w0, Wlo + o_l1w0, SL, 256, lin1_b0, nullptr, 0, NN,     256, 256, 0);
    launch_tc(VG1, 256, Whi + o_l1w1, Wlo + o_l1w1, VL, 256, nullptr, nullptr, 0, 3 * NN, 256, 256, 0);
    launch_tc(G2,  512, Whi + o_l2w0, Wlo + o_l2w0, SR, 256, lin2_b0, nullptr, 0, NN,     256, 256, 0);
    launch_tc(VG2, 256, Whi + o_l2w1, Wlo + o_l2w1, VR, 256, nullptr, nullptr, 0, 3 * NN, 256, 256, 0);

    // Stage 5: tensor product + resnet
    tp_kernel<<<NN, 256>>>(SL, VL, SR, VR, F0, V, tp_w, F0t, Vt);

    // Stage 6: output NormGate
    launch_tc(F0t, 512, Whi + o_ngow1, Wlo + o_ngow1, H3, 512, ngo_b1, nullptr, 0, NN, 512, 512, 1);
    launch_tc(H3,  512, Whi + o_ngow2, Wlo + o_ngow2, G3, 512, ngo_b2, nullptr, 0, NN, 512, 512, 0);
    gate_kernel<<<NN * 3, 256>>>(Vt, G3, VG3);

    // Stage 7: final irrep linear + old_fii residual
    launch_tc(G3,  512, Whi + o_l3w0, Wlo + o_l3w0, out, 1024, lin3_b0, old_fii, 1024, NN, 256, 256, 0);
    launch_tc(VG3, 256, Whi + o_l3w1, Wlo + o_l3w1, VO3, 256, nullptr, nullptr, 0, 3 * NN, 256, 256, 0);
    final_kernel<<<NN * 3, 256>>>(VO3, old_fii, out);
}

// round 14
// speedup vs baseline: 1.5220x; 1.1472x over previous
#include <cuda_runtime.h>
#include <cuda_bf16.h>
#include <mma.h>
#include <math.h>
#include <string.h>
#include <stdint.h>

using namespace nvcuda;

// Problem constants
#define NN   32768

// ---------------- scratch (allocation-free: __device__ globals) ----------------
__device__ float g_F0 [NN*512];
__device__ float g_V  [NN*768];
__device__ float g_H1 [NN*512];
__device__ float g_H2 [NN*512];
__device__ float g_G1 [NN*512];
__device__ float g_G2 [NN*512];
__device__ float g_VG1[NN*768];
__device__ float g_VG2[NN*768];
__device__ float g_SL [NN*256];
__device__ float g_SR [NN*256];
__device__ float g_VL [NN*768];
__device__ float g_VR [NN*768];
__device__ float g_F0t[NN*512];
__device__ float g_Vt [NN*768];
__device__ float g_H3 [NN*512];
__device__ float g_G3 [NN*512];
__device__ float g_VG3[NN*768];
__device__ float g_VO3[NN*768];

// converted weights: [Nc][K] bf16 (n-major rows, k contiguous), alpha folded in
#define WTOTAL 1966080
__device__ __nv_bfloat16 g_Whi[WTOTAL];
__device__ __nv_bfloat16 g_Wlo[WTOTAL];

// ---------------- helpers ----------------
__device__ __forceinline__ uint32_t s2u(const void* p) {
    return (uint32_t)__cvta_generic_to_shared(p);
}
__device__ __forceinline__ void cp_async16(uint32_t smem_addr, const void* gptr) {
    asm volatile("cp.async.cg.shared.global [%0], [%1], 16;"
                 :: "r"(smem_addr), "l"(gptr) : "memory");
}
#define CP_COMMIT()   asm volatile("cp.async.commit_group;" ::: "memory")
#define CP_WAIT_ALL() asm volatile("cp.async.wait_group 0;" ::: "memory")

// ---------------- wmma split-bf16 GEMM, double-buffered + cp.async B ---------
// C[M,Nc] = act( A[M,K](fp32) @ Wt^T + bias + res ), Wt = [Nc][K] bf16 hi/lo
// SMEM per stage (bf16, padded leading dim LDE=40 elements = 80 B):
//   AH [128][40] row-major, AL, BH [128][40] n-rows/k-contig, BL
// stage 40960 B; 2 stages = 81920 B dynamic (opt-in). 2 CTAs/SM target.
// grid = (Nc/128, M/128), 256 threads = 8 warps in 2(m) x 4(n); warp tile 64x32.
#define LDE 40
#define STAGE_E 20480
#define GEMM_SMEM 81920

__global__ void __launch_bounds__(256, 2)
gemm_tc(const float* __restrict__ A, int lda,
        const __nv_bfloat16* __restrict__ Bhi,
        const __nv_bfloat16* __restrict__ Blo,
        float* __restrict__ C, int ldc,
        const float* __restrict__ bias,
        const float* __restrict__ res, int ldres,
        int K, int act)
{
    extern __shared__ __align__(16) __nv_bfloat16 smx[];

    const int tid  = threadIdx.x;
    const int wid  = tid >> 5;
    const int wm   = wid & 1;    // 0..1 : 64 rows each
    const int wn   = wid >> 1;   // 0..3 : 32 cols each
    const int block_m = blockIdx.y * 128;
    const int block_n = blockIdx.x * 128;

    wmma::fragment<wmma::accumulator, 16, 16, 16, float> acc[4][2];
#pragma unroll
    for (int mi = 0; mi < 4; ++mi)
#pragma unroll
        for (int ni = 0; ni < 2; ++ni)
            wmma::fill_fragment(acc[mi][ni], 0.0f);

    float4 aR[4];           // A prefetch: 128 rows x 32 k fp32

    const int nk = K >> 5;

    auto LDG_A = [&](int k0) {
#pragma unroll
        for (int it = 0; it < 4; ++it) {
            int id = it * 256 + tid, row = id >> 3, c4 = id & 7;
            aR[it] = *reinterpret_cast<const float4*>(
                A + (size_t)(block_m + row) * lda + k0 + c4 * 4);
        }
    };
    auto STS_A = [&](int s) {
        __nv_bfloat16* AH = smx + s * STAGE_E;
        __nv_bfloat16* AL = AH + 5120;
#pragma unroll
        for (int it = 0; it < 4; ++it) {
            int id = it * 256 + tid, row = id >> 3, c4 = id & 7;
            float av[4] = {aR[it].x, aR[it].y, aR[it].z, aR[it].w};
#pragma unroll
            for (int q = 0; q < 4; ++q) {
                float v = av[q];
                __nv_bfloat16 h = __float2bfloat16(v);
                __nv_bfloat16 l = __float2bfloat16(v - __bfloat162float(h));
                AH[row * LDE + c4 * 4 + q] = h;
                AL[row * LDE + c4 * 4 + q] = l;
            }
        }
    };
    auto CP_B = [&](int s, int k0) {
        uint32_t bh_base = s2u(smx + s * STAGE_E + 10240);
        uint32_t bl_base = s2u(smx + s * STAGE_E + 15360);
#pragma unroll
        for (int it = 0; it < 2; ++it) {
            int id = it * 256 + tid, nrow = id >> 2, c = id & 3;   // c*8 bf16 = 16B
            size_t off = (size_t)(block_n + nrow) * K + k0 + c * 8;
            uint32_t so = (uint32_t)(nrow * 80 + c * 16);
            cp_async16(bh_base + so, Bhi + off);
            cp_async16(bl_base + so, Blo + off);
        }
    };
    auto COMPUTE = [&](int s) {
        const __nv_bfloat16* AH = smx + s * STAGE_E;
        const __nv_bfloat16* AL = AH + 5120;
        const __nv_bfloat16* BH = AH + 10240;
        const __nv_bfloat16* BL = AH + 15360;
#pragma unroll
        for (int ks = 0; ks < 2; ++ks) {
            const int kofs = ks * 16;
            wmma::fragment<wmma::matrix_a, 16, 16, 16, __nv_bfloat16, wmma::row_major> fah[4], fal[4];
#pragma unroll
            for (int mi = 0; mi < 4; ++mi) {
                wmma::load_matrix_sync(fah[mi], AH + (wm * 64 + mi * 16) * LDE + kofs, LDE);
                wmma::load_matrix_sync(fal[mi], AL + (wm * 64 + mi * 16) * LDE + kofs, LDE);
            }
#pragma unroll
            for (int ni = 0; ni < 2; ++ni) {
                wmma::fragment<wmma::matrix_b, 16, 16, 16, __nv_bfloat16, wmma::col_major> fbh, fbl;
                wmma::load_matrix_sync(fbh, BH + (wn * 32 + ni * 16) * LDE + kofs, LDE);
                wmma::load_matrix_sync(fbl, BL + (wn * 32 + ni * 16) * LDE + kofs, LDE);
#pragma unroll
                for (int mi = 0; mi < 4; ++mi) {
                    wmma::mma_sync(acc[mi][ni], fah[mi], fbh, acc[mi][ni]);
                    wmma::mma_sync(acc[mi][ni], fah[mi], fbl, acc[mi][ni]);
                    wmma::mma_sync(acc[mi][ni], fal[mi], fbh, acc[mi][ni]);
                }
            }
        }
    };

    // prologue
    CP_B(0, 0);
    CP_COMMIT();
    LDG_A(0);
    STS_A(0);
    CP_WAIT_ALL();
    __syncthreads();

    for (int it = 0; it < nk; ++it) {
        if (it + 1 < nk) {
            LDG_A((it + 1) << 5);            // A prefetch into regs
            CP_B((it + 1) & 1, (it + 1) << 5); // B async into other stage
            CP_COMMIT();
        }
        COMPUTE(it & 1);
        if (it + 1 < nk) STS_A((it + 1) & 1);
        CP_WAIT_ALL();                        // next stage's B landed
        __syncthreads();
    }

    // ---- epilogue: two half-tile passes through SMEM (64 x 128 f32 = 32 KB) ----
    float* sf = reinterpret_cast<float*>(smx);
    __syncthreads();
#pragma unroll
    for (int pass = 0; pass < 2; ++pass) {
        if (wm == pass) {
#pragma unroll
            for (int mi = 0; mi < 4; ++mi)
#pragma unroll
                for (int ni = 0; ni < 2; ++ni)
                    wmma::store_matrix_sync(sf + (mi * 16) * 128 + wn * 32 + ni * 16,
                                            acc[mi][ni], 128, wmma::mem_row_major);
        }
        __syncthreads();
        for (int i = tid; i < 2048; i += 256) {   // 64 rows x 32 float4
            int r = i >> 5, c4 = (i & 31) * 4;
            float4 v = *reinterpret_cast<float4*>(sf + r * 128 + c4);
            int row = block_m + pass * 64 + r;
            int col = block_n + c4;
            float vv[4] = {v.x, v.y, v.z, v.w};
#pragma unroll
            for (int j = 0; j < 4; ++j) {
                float t = vv[j];
                if (bias) t += bias[col + j];
                if (res)  t += res[(size_t)row * ldres + col + j];
                if (act)  t = t / (1.0f + __expf(-t));
                vv[j] = t;
            }
            float4 o; o.x = vv[0]; o.y = vv[1]; o.z = vv[2]; o.w = vv[3];
            *reinterpret_cast<float4*>(C + (size_t)row * ldc + col) = o;
        }
        __syncthreads();
    }
}

// ---------------- batched weight conversion ----------------------------------
// Converts 6 weight matrices [K,Nc] fp32 -> [Nc][K] bf16 hi/lo in ONE launch.
__global__ void convert_w6(const float* w0, const float* w1, const float* w2,
                           const float* w3, const float* w4, const float* w5,
                           __nv_bfloat16* __restrict__ hi,
                           __nv_bfloat16* __restrict__ lo,
                           int K, int Nc, float scale, int stride_e)
{
    int per = K * Nc;
    int gidx = blockIdx.x * blockDim.x + threadIdx.x;
    if (gidx >= 6 * per) return;
    int which = gidx / per;
    int idx = gidx - which * per;
    const float* W;
    switch (which) {
        case 0: W = w0; break;
        case 1: W = w1; break;
        case 2: W = w2; break;
        case 3: W = w3; break;
        case 4: W = w4; break;
        default: W = w5; break;
    }
    int n = idx / K, k = idx % K;
    float v = W[(size_t)k * Nc + n] * scale;
    __nv_bfloat16 h = __float2bfloat16(v);
    float rlo = v - __bfloat162float(h);
    size_t o = (size_t)which * stride_e + idx;
    hi[o] = h;
    lo[o] = __float2bfloat16(rlo);
}

// ---------------- elementwise kernels (verified) ----------------
__global__ void prep_kernel(const float* __restrict__ x,
                            float* __restrict__ F0, float* __restrict__ V)
{
    const int n = blockIdx.x;
    const int u = threadIdx.x;
    const float* xr = x + (size_t)n * 1024;
    float s  = xr[u];
    float v0 = xr[256 + 3 * u + 0];
    float v1 = xr[256 + 3 * u + 1];
    float v2 = xr[256 + 3 * u + 2];
    F0[(size_t)n * 512 + u]       = s;
    F0[(size_t)n * 512 + 256 + u] = sqrtf(v0 * v0 + v1 * v1 + v2 * v2 + 1e-12f);
    size_t vb = ((size_t)3 * n) * 256 + u;
    V[vb]       = v0;
    V[vb + 256] = v1;
    V[vb + 512] = v2;
}

__global__ void gate_kernel(const float* __restrict__ V,
                            const float* __restrict__ G,
                            float* __restrict__ VG)
{
    size_t idx = (size_t)blockIdx.x * blockDim.x + threadIdx.x;
    int u = (int)(idx & 255);
    size_t r = idx >> 8;
    size_t n = r / 3;
    VG[idx] = V[idx] * G[n * 512 + 256 + u];
}

__global__ void tp_kernel(const float* __restrict__ SL, const float* __restrict__ VL,
                          const float* __restrict__ SR, const float* __restrict__ VR,
                          const float* __restrict__ F0, const float* __restrict__ V,
                          const float* __restrict__ tpw,
                          float* __restrict__ F0t, float* __restrict__ Vt)
{
    const int n = blockIdx.x;
    const int u = threadIdx.x;
    const size_t b256 = (size_t)n * 256 + u;
    const size_t b512 = (size_t)n * 512 + u;
    const size_t vb   = ((size_t)3 * n) * 256 + u;

    float s1 = SL[b256], s2 = SR[b256];
    float ax = VL[vb], ay = VL[vb + 256], az = VL[vb + 512];
    float bx = VR[vb], by = VR[vb + 256], bz = VR[vb + 512];
    float w0 = tpw[u], w1 = tpw[256 + u], w2 = tpw[512 + u],
          w3 = tpw[768 + u], w4 = tpw[1024 + u];

    const float A0 = 0.44721359549995793f;
    const float A1 = 0.77459666924148340f;
    const float I3 = 0.57735026918962576f;
    const float I6 = 0.40824829046386302f;

    float dot = ax * bx + ay * by + az * bz;
    float t0 = A0 * (w0 * s1 * s2 + w3 * I3 * dot) + F0[b512];

    float cx = ay * bz - az * by;
    float cy = az * bx - ax * bz;
    float cz = ax * by - ay * bx;
    float k1 = A1 * I3 * w1 * s1;
    float k2 = A1 * I3 * w2 * s2;
    float k4 = A1 * I6 * w4;
    float tx = k1 * bx + k2 * ax + k4 * cx + V[vb];
    float ty = k1 * by + k2 * ay + k4 * cy + V[vb + 256];
    float tz = k1 * bz + k2 * az + k4 * cz + V[vb + 512];

    F0t[b512]       = t0;
    F0t[b512 + 256] = sqrtf(tx * tx + ty * ty + tz * tz + 1e-12f);
    Vt[vb]       = tx;
    Vt[vb + 256] = ty;
    Vt[vb + 512] = tz;
}

__global__ void final_kernel(const float* __restrict__ VO3,
                             const float* __restrict__ old_fii,
                             float* __restrict__ out)
{
    size_t idx = (size_t)blockIdx.x * blockDim.x + threadIdx.x;
    size_t n = idx / 768;
    int j = (int)(idx % 768);
    int u = j / 3;
    int i = j % 3;
    size_t o = n * 1024 + 256 + j;
    out[o] = old_fii[o] + VO3[((size_t)3 * n + i) * 256 + u];
}

// ---------------- host launch ----------------
static inline void launch_tc(const float* A, int lda,
                             const __nv_bfloat16* bh, const __nv_bfloat16* bl,
                             float* C, int ldc, const float* bias,
                             const float* res, int ldres,
                             int M, int Nc, int K, int act)
{
    dim3 grid(Nc / 128, M / 128);
    gemm_tc<<<grid, 256, GEMM_SMEM>>>(A, lda, bh, bl, C, ldc, bias, res, ldres, K, act);
}

extern "C" void kernel_launch(void* const* d_in, const int* in_sizes, int n_in,
                              void* d_out, int out_size)
{
    const float* x       = (const float*)d_in[0];
    const float* old_fii = (const float*)d_in[1];
    const float* ng1_w1 = (const float*)d_in[2];
    const float* ng1_b1 = (const float*)d_in[3];
    const float* ng1_w2 = (const float*)d_in[4];
    const float* ng1_b2 = (const float*)d_in[5];
    const float* ng2_w1 = (const float*)d_in[6];
    const float* ng2_b1 = (const float*)d_in[7];
    const float* ng2_w2 = (const float*)d_in[8];
    const float* ng2_b2 = (const float*)d_in[9];
    const float* ngo_w1 = (const float*)d_in[10];
    const float* ngo_b1 = (const float*)d_in[11];
    const float* ngo_w2 = (const float*)d_in[12];
    const float* ngo_b2 = (const float*)d_in[13];
    const float* lin1_w0 = (const float*)d_in[14];
    const float* lin1_b0 = (const float*)d_in[15];
    const float* lin1_w1 = (const float*)d_in[16];
    const float* lin2_w0 = (const float*)d_in[17];
    const float* lin2_b0 = (const float*)d_in[18];
    const float* lin2_w1 = (const float*)d_in[19];
    const float* lin3_w0 = (const float*)d_in[20];
    const float* lin3_b0 = (const float*)d_in[21];
    const float* lin3_w1 = (const float*)d_in[22];
    const float* tp_w    = (const float*)d_in[23];
    float* out = (float*)d_out;

    cudaFuncSetAttribute(gemm_tc, cudaFuncAttributeMaxDynamicSharedMemorySize, GEMM_SMEM);

    float *F0, *V, *H1, *H2, *G1, *G2, *VG1, *VG2, *SL, *SR, *VL, *VR,
          *F0t, *Vt, *H3, *G3, *VG3, *VO3;
    __nv_bfloat16 *Whi, *Wlo;
    cudaGetSymbolAddress((void**)&F0,  g_F0);
    cudaGetSymbolAddress((void**)&V,   g_V);
    cudaGetSymbolAddress((void**)&H1,  g_H1);
    cudaGetSymbolAddress((void**)&H2,  g_H2);
    cudaGetSymbolAddress((void**)&G1,  g_G1);
    cudaGetSymbolAddress((void**)&G2,  g_G2);
    cudaGetSymbolAddress((void**)&VG1, g_VG1);
    cudaGetSymbolAddress((void**)&VG2, g_VG2);
    cudaGetSymbolAddress((void**)&SL,  g_SL);
    cudaGetSymbolAddress((void**)&SR,  g_SR);
    cudaGetSymbolAddress((void**)&VL,  g_VL);
    cudaGetSymbolAddress((void**)&VR,  g_VR);
    cudaGetSymbolAddress((void**)&F0t, g_F0t);
    cudaGetSymbolAddress((void**)&Vt,  g_Vt);
    cudaGetSymbolAddress((void**)&H3,  g_H3);
    cudaGetSymbolAddress((void**)&G3,  g_G3);
    cudaGetSymbolAddress((void**)&VG3, g_VG3);
    cudaGetSymbolAddress((void**)&VO3, g_VO3);
    cudaGetSymbolAddress((void**)&Whi, g_Whi);
    cudaGetSymbolAddress((void**)&Wlo, g_Wlo);

    // weight scratch offsets (elements)
    const int OB = 262144;  // 512*512
    const int OS = 65536;   // 256*256
    const int o_ng1w1 = 0,        o_ng2w1 = OB,       o_ng1w2 = 2*OB,
              o_ng2w2 = 3*OB,     o_ngow1 = 4*OB,     o_ngow2 = 5*OB;
    const int o_l1w0 = 6*OB,          o_l1w1 = 6*OB + OS,   o_l2w0 = 6*OB + 2*OS,
              o_l2w1 = 6*OB + 3*OS,   o_l3w0 = 6*OB + 4*OS, o_l3w1 = 6*OB + 5*OS;

    const float inv16 = 0.0625f;  // 1/sqrt(256), folded into lin weights

    // ---- convert weights once (2 batched launches) ----
    {
        const int T = 256;
        int nb = (6 * 512 * 512 + T - 1) / T;
        convert_w6<<<nb, T>>>(ng1_w1, ng2_w1, ng1_w2, ng2_w2, ngo_w1, ngo_w2,
                              Whi, Wlo, 512, 512, 1.f, OB);
        int ns = (6 * 256 * 256 + T - 1) / T;
        convert_w6<<<ns, T>>>(lin1_w0, lin1_w1, lin2_w0, lin2_w1, lin3_w0, lin3_w1,
                              Whi + 6 * OB, Wlo + 6 * OB, 256, 256, inv16, OS);
    }

    // Stage 1: prep
    prep_kernel<<<NN, 256>>>(x, F0, V);

    // Stage 2: NormGate MLPs (left/right)
    launch_tc(F0, 512, Whi + o_ng1w1, Wlo + o_ng1w1, H1, 512, ng1_b1, nullptr, 0, NN, 512, 512, 1);
    launch_tc(F0, 512, Whi + o_ng2w1, Wlo + o_ng2w1, H2, 512, ng2_b1, nullptr, 0, NN, 512, 512, 1);
    launch_tc(H1, 512, Whi + o_ng1w2, Wlo + o_ng1w2, G1, 512, ng1_b2, nullptr, 0, NN, 512, 512, 0);
    launch_tc(H2, 512, Whi + o_ng2w2, Wlo + o_ng2w2, G2, 512, ng2_b2, nullptr, 0, NN, 512, 512, 0);

    // Stage 3: gate vectors
    gate_kernel<<<NN * 3, 256>>>(V, G1, VG1);
    gate_kernel<<<NN * 3, 256>>>(V, G2, VG2);

    // Stage 4: irrep linears
    launch_tc(G1,  512, Whi + o_l1w0, Wlo + o_l1w0, SL, 256, lin1_b0, nullptr, 0, NN,     256, 256, 0);
    launch_tc(VG1, 256, Whi + o_l1w1, Wlo + o_l1w1, VL, 256, nullptr, nullptr, 0, 3 * NN, 256, 256, 0);
    launch_tc(G2,  512, Whi + o_l2w0, Wlo + o_l2w0, SR, 256, lin2_b0, nullptr, 0, NN,     256, 256, 0);
    launch_tc(VG2, 256, Whi + o_l2w1, Wlo + o_l2w1, VR, 256, nullptr, nullptr, 0, 3 * NN, 256, 256, 0);

    // Stage 5: tensor product + resnet
    tp_kernel<<<NN, 256>>>(SL, VL, SR, VR, F0, V, tp_w, F0t, Vt);

    // Stage 6: output NormGate
    launch_tc(F0t, 512, Whi + o_ngow1, Wlo + o_ngow1, H3, 512, ngo_b1, nullptr, 0, NN, 512, 512, 1);
    launch_tc(H3,  512, Whi + o_ngow2, Wlo + o_ngow2, G3, 512, ngo_b2, nullptr, 0, NN, 512, 512, 0);
    gate_kernel<<<NN * 3, 256>>>(Vt, G3, VG3);

    // Stage 7: final irrep linear + old_fii residual
    launch_tc(G3,  512, Whi + o_l3w0, Wlo + o_l3w0, out, 1024, lin3_b0, old_fii, 1024, NN, 256, 256, 0);
    launch_tc(VG3, 256, Whi + o_l3w1, Wlo + o_l3w1, VO3, 256, nullptr, nullptr, 0, 3 * NN, 256, 256, 0);
    final_kernel<<<NN * 3, 256>>>(VO3, old_fii, out);
}

// round 15
// speedup vs baseline: 1.7807x; 1.1700x over previous
#include <cuda_runtime.h>
#include <cuda_bf16.h>
#include <mma.h>
#include <math.h>
#include <string.h>
#include <stdint.h>

using namespace nvcuda;

// Problem constants
#define NN   32768

typedef __nv_bfloat16 bf16;

// ---------------- scratch (allocation-free: __device__ globals) ----------------
// bf16 hi/lo pairs for every GEMM A-operand / GEMM hi-lo output
__device__ bf16 g_F0h [NN*512];  __device__ bf16 g_F0l [NN*512];
__device__ bf16 g_H1h [NN*512];  __device__ bf16 g_H1l [NN*512];
__device__ bf16 g_H2h [NN*512];  __device__ bf16 g_H2l [NN*512];
__device__ bf16 g_H3h [NN*512];  __device__ bf16 g_H3l [NN*512];
__device__ bf16 g_G1h [NN*512];  __device__ bf16 g_G1l [NN*512];
__device__ bf16 g_G2h [NN*512];  __device__ bf16 g_G2l [NN*512];
__device__ bf16 g_G3h [NN*512];  __device__ bf16 g_G3l [NN*512];
__device__ bf16 g_VG1h[NN*768];  __device__ bf16 g_VG1l[NN*768];
__device__ bf16 g_VG2h[NN*768];  __device__ bf16 g_VG2l[NN*768];
__device__ bf16 g_VG3h[NN*768];  __device__ bf16 g_VG3l[NN*768];
__device__ bf16 g_F0th[NN*512];  __device__ bf16 g_F0tl[NN*512];
// fp32 scratch
__device__ float g_V  [NN*768];
__device__ float g_Vt [NN*768];
__device__ float g_SL [NN*256];
__device__ float g_SR [NN*256];
__device__ float g_VL [NN*768];
__device__ float g_VR [NN*768];
__device__ float g_VO3[NN*768];

// converted weights: [Nc][K] bf16 (n-major rows, k contiguous), alpha folded in
#define WTOTAL 1966080
__device__ bf16 g_Whi[WTOTAL];
__device__ bf16 g_Wlo[WTOTAL];

// ---------------- helpers ----------------
__device__ __forceinline__ uint32_t s2u(const void* p) {
    return (uint32_t)__cvta_generic_to_shared(p);
}
__device__ __forceinline__ void cp_async16(uint32_t smem_addr, const void* gptr) {
    asm volatile("cp.async.cg.shared.global [%0], [%1], 16;"
                 :: "r"(smem_addr), "l"(gptr) : "memory");
}
#define CP_COMMIT()   asm volatile("cp.async.commit_group;" ::: "memory")
#define CP_WAIT_ALL() asm volatile("cp.async.wait_group 0;" ::: "memory")

__device__ __forceinline__ void split_bf16(float v, bf16& h, bf16& l) {
    h = __float2bfloat16(v);
    l = __float2bfloat16(v - __bfloat162float(h));
}

// ---------------- wmma split-bf16 GEMM: pure cp.async mainloop ---------------
// C = act( (Ahi+Alo)[M,K] @ (Whi+Wlo)^T + bias + res )
// A given as bf16 hi/lo [M][lda]; W as [Nc][K] bf16 hi/lo.
// Outputs: Cf fp32 (optional) and/or Chi/Clo bf16 split (optional).
// SMEM per stage: AH/AL/BH/BL [128][LDE=40] bf16 → 40960 B; 2 stages = 81920 B.
// grid = (Nc/128, M/128), 256 threads = 8 warps in 2(m) x 4(n).
#define LDE 40
#define STAGE_E 20480
#define GEMM_SMEM 81920

__global__ void __launch_bounds__(256, 2)
gemm_tc(const bf16* __restrict__ Ahi, const bf16* __restrict__ Alo, int lda,
        const bf16* __restrict__ Bhi, const bf16* __restrict__ Blo, int ldb,
        float* __restrict__ Cf, int ldc,
        bf16* __restrict__ Chi, bf16* __restrict__ Clo, int ldc2,
        const float* __restrict__ bias,
        const float* __restrict__ res, int ldres,
        int K, int act)
{
    extern __shared__ __align__(16) bf16 smx[];

    const int tid  = threadIdx.x;
    const int wid  = tid >> 5;
    const int wm   = wid & 1;
    const int wn   = wid >> 1;
    const int block_m = blockIdx.y * 128;
    const int block_n = blockIdx.x * 128;

    wmma::fragment<wmma::accumulator, 16, 16, 16, float> acc[4][2];
#pragma unroll
    for (int mi = 0; mi < 4; ++mi)
#pragma unroll
        for (int ni = 0; ni < 2; ++ni)
            wmma::fill_fragment(acc[mi][ni], 0.0f);

    const int nk = K >> 5;

    auto CP_T = [&](int s, int k0) {
        uint32_t ah = s2u(smx) + s * (STAGE_E * 2);   // byte offsets
        uint32_t al = ah + 10240;
        uint32_t bh = ah + 20480;
        uint32_t bl = ah + 30720;
#pragma unroll
        for (int it = 0; it < 2; ++it) {
            int id = it * 256 + tid, row = id >> 2, c = id & 3;  // c*8 bf16 = 16B
            uint32_t so = (uint32_t)(row * 80 + c * 16);
            size_t ao = (size_t)(block_m + row) * lda + k0 + c * 8;
            cp_async16(ah + so, Ahi + ao);
            cp_async16(al + so, Alo + ao);
            size_t bo = (size_t)(block_n + row) * ldb + k0 + c * 8;
            cp_async16(bh + so, Bhi + bo);
            cp_async16(bl + so, Blo + bo);
        }
    };
    auto COMPUTE = [&](int s) {
        const bf16* AH = smx + s * STAGE_E;
        const bf16* AL = AH + 5120;
        const bf16* BH = AH + 10240;
        const bf16* BL = AH + 15360;
#pragma unroll
        for (int ks = 0; ks < 2; ++ks) {
            const int kofs = ks * 16;
            wmma::fragment<wmma::matrix_a, 16, 16, 16, bf16, wmma::row_major> fah[4], fal[4];
#pragma unroll
            for (int mi = 0; mi < 4; ++mi) {
                wmma::load_matrix_sync(fah[mi], AH + (wm * 64 + mi * 16) * LDE + kofs, LDE);
                wmma::load_matrix_sync(fal[mi], AL + (wm * 64 + mi * 16) * LDE + kofs, LDE);
            }
#pragma unroll
            for (int ni = 0; ni < 2; ++ni) {
                wmma::fragment<wmma::matrix_b, 16, 16, 16, bf16, wmma::col_major> fbh, fbl;
                wmma::load_matrix_sync(fbh, BH + (wn * 32 + ni * 16) * LDE + kofs, LDE);
                wmma::load_matrix_sync(fbl, BL + (wn * 32 + ni * 16) * LDE + kofs, LDE);
#pragma unroll
                for (int mi = 0; mi < 4; ++mi) {
                    wmma::mma_sync(acc[mi][ni], fah[mi], fbh, acc[mi][ni]);
                    wmma::mma_sync(acc[mi][ni], fah[mi], fbl, acc[mi][ni]);
                    wmma::mma_sync(acc[mi][ni], fal[mi], fbh, acc[mi][ni]);
                }
            }
        }
    };

    CP_T(0, 0);
    CP_COMMIT();
    CP_WAIT_ALL();
    __syncthreads();

    for (int it = 0; it < nk; ++it) {
        if (it + 1 < nk) {
            CP_T((it + 1) & 1, (it + 1) << 5);
            CP_COMMIT();
        }
        COMPUTE(it & 1);
        CP_WAIT_ALL();
        __syncthreads();
    }

    // ---- epilogue: two half-tile passes through SMEM ----
    float* sf = reinterpret_cast<float*>(smx);
    __syncthreads();
#pragma unroll
    for (int pass = 0; pass < 2; ++pass) {
        if (wm == pass) {
#pragma unroll
            for (int mi = 0; mi < 4; ++mi)
#pragma unroll
                for (int ni = 0; ni < 2; ++ni)
                    wmma::store_matrix_sync(sf + (mi * 16) * 128 + wn * 32 + ni * 16,
                                            acc[mi][ni], 128, wmma::mem_row_major);
        }
        __syncthreads();
        for (int i = tid; i < 2048; i += 256) {   // 64 rows x 32 float4
            int r = i >> 5, c4 = (i & 31) * 4;
            float4 v = *reinterpret_cast<float4*>(sf + r * 128 + c4);
            int row = block_m + pass * 64 + r;
            int col = block_n + c4;
            float vv[4] = {v.x, v.y, v.z, v.w};
#pragma unroll
            for (int j = 0; j < 4; ++j) {
                float t = vv[j];
                if (bias) t += bias[col + j];
                if (res)  t += res[(size_t)row * ldres + col + j];
                if (act)  t = t / (1.0f + __expf(-t));
                vv[j] = t;
            }
            if (Cf) {
                float4 o; o.x = vv[0]; o.y = vv[1]; o.z = vv[2]; o.w = vv[3];
                *reinterpret_cast<float4*>(Cf + (size_t)row * ldc + col) = o;
            }
            if (Chi) {
                bf16 h[4], l[4];
#pragma unroll
                for (int j = 0; j < 4; ++j) split_bf16(vv[j], h[j], l[j]);
                *reinterpret_cast<uint2*>(Chi + (size_t)row * ldc2 + col) =
                    *reinterpret_cast<uint2*>(h);
                *reinterpret_cast<uint2*>(Clo + (size_t)row * ldc2 + col) =
                    *reinterpret_cast<uint2*>(l);
            }
        }
        __syncthreads();
    }
}

// ---------------- batched weight conversion ----------------------------------
__global__ void convert_w6(const float* w0, const float* w1, const float* w2,
                           const float* w3, const float* w4, const float* w5,
                           bf16* __restrict__ hi, bf16* __restrict__ lo,
                           int K, int Nc, float scale, int stride_e)
{
    int per = K * Nc;
    int gidx = blockIdx.x * blockDim.x + threadIdx.x;
    if (gidx >= 6 * per) return;
    int which = gidx / per;
    int idx = gidx - which * per;
    const float* W;
    switch (which) {
        case 0: W = w0; break;
        case 1: W = w1; break;
        case 2: W = w2; break;
        case 3: W = w3; break;
        case 4: W = w4; break;
        default: W = w5; break;
    }
    int n = idx / K, k = idx % K;
    float v = W[(size_t)k * Nc + n] * scale;
    bf16 h, l; split_bf16(v, h, l);
    size_t o = (size_t)which * stride_e + idx;
    hi[o] = h;
    lo[o] = l;
}

// ---------------- elementwise kernels ----------------
// x[N,1024] -> F0 hi/lo [N,512]=[s,|v|], V[N,3,256] planar fp32
__global__ void prep_kernel(const float* __restrict__ x,
                            bf16* __restrict__ F0h, bf16* __restrict__ F0l,
                            float* __restrict__ V)
{
    const int n = blockIdx.x;
    const int u = threadIdx.x;
    const float* xr = x + (size_t)n * 1024;
    float s  = xr[u];
    float v0 = xr[256 + 3 * u + 0];
    float v1 = xr[256 + 3 * u + 1];
    float v2 = xr[256 + 3 * u + 2];
    float nv = sqrtf(v0 * v0 + v1 * v1 + v2 * v2 + 1e-12f);
    bf16 h, l;
    split_bf16(s,  h, l); F0h[(size_t)n * 512 + u] = h;        F0l[(size_t)n * 512 + u] = l;
    split_bf16(nv, h, l); F0h[(size_t)n * 512 + 256 + u] = h;  F0l[(size_t)n * 512 + 256 + u] = l;
    size_t vb = ((size_t)3 * n) * 256 + u;
    V[vb]       = v0;
    V[vb + 256] = v1;
    V[vb + 512] = v2;
}

// VG = V * (Ghi+Glo)[:,256+u], output hi/lo
__global__ void gate_kernel(const float* __restrict__ V,
                            const bf16* __restrict__ Gh, const bf16* __restrict__ Gl,
                            bf16* __restrict__ VGh, bf16* __restrict__ VGl)
{
    size_t idx = (size_t)blockIdx.x * blockDim.x + threadIdx.x;
    int u = (int)(idx & 255);
    size_t r = idx >> 8;
    size_t n = r / 3;
    size_t go = n * 512 + 256 + u;
    float g = __bfloat162float(Gh[go]) + __bfloat162float(Gl[go]);
    float v = V[idx] * g;
    bf16 h, l; split_bf16(v, h, l);
    VGh[idx] = h;
    VGl[idx] = l;
}

// tensor product + resnet(x) + norms; outputs F0t hi/lo + Vt fp32
__global__ void tp_kernel(const float* __restrict__ SL, const float* __restrict__ VL,
                          const float* __restrict__ SR, const float* __restrict__ VR,
                          const float* __restrict__ x, const float* __restrict__ V,
                          const float* __restrict__ tpw,
                          bf16* __restrict__ F0th, bf16* __restrict__ F0tl,
                          float* __restrict__ Vt)
{
    const int n = blockIdx.x;
    const int u = threadIdx.x;
    const size_t b256 = (size_t)n * 256 + u;
    const size_t b512 = (size_t)n * 512 + u;
    const size_t vb   = ((size_t)3 * n) * 256 + u;

    float s1 = SL[b256], s2 = SR[b256];
    float ax = VL[vb], ay = VL[vb + 256], az = VL[vb + 512];
    float bx = VR[vb], by = VR[vb + 256], bz = VR[vb + 512];
    float w0 = tpw[u], w1 = tpw[256 + u], w2 = tpw[512 + u],
          w3 = tpw[768 + u], w4 = tpw[1024 + u];

    const float A0 = 0.44721359549995793f;
    const float A1 = 0.77459666924148340f;
    const float I3 = 0.57735026918962576f;
    const float I6 = 0.40824829046386302f;

    float dot = ax * bx + ay * by + az * bz;
    float t0 = A0 * (w0 * s1 * s2 + w3 * I3 * dot) + x[(size_t)n * 1024 + u];

    float cx = ay * bz - az * by;
    float cy = az * bx - ax * bz;
    float cz = ax * by - ay * bx;
    float k1 = A1 * I3 * w1 * s1;
    float k2 = A1 * I3 * w2 * s2;
    float k4 = A1 * I6 * w4;
    float tx = k1 * bx + k2 * ax + k4 * cx + V[vb];
    float ty = k1 * by + k2 * ay + k4 * cy + V[vb + 256];
    float tz = k1 * bz + k2 * az + k4 * cz + V[vb + 512];

    float nv = sqrtf(tx * tx + ty * ty + tz * tz + 1e-12f);
    bf16 h, l;
    split_bf16(t0, h, l); F0th[b512] = h;        F0tl[b512] = l;
    split_bf16(nv, h, l); F0th[b512 + 256] = h;  F0tl[b512 + 256] = l;
    Vt[vb]       = tx;
    Vt[vb + 256] = ty;
    Vt[vb + 512] = tz;
}

__global__ void final_kernel(const float* __restrict__ VO3,
                             const float* __restrict__ old_fii,
                             float* __restrict__ out)
{
    size_t idx = (size_t)blockIdx.x * blockDim.x + threadIdx.x;
    size_t n = idx / 768;
    int j = (int)(idx % 768);
    int u = j / 3;
    int i = j % 3;
    size_t o = n * 1024 + 256 + j;
    out[o] = old_fii[o] + VO3[((size_t)3 * n + i) * 256 + u];
}

// ---------------- host launch ----------------
static inline void launch_tc(const bf16* ah, const bf16* al, int lda,
                             const bf16* bh, const bf16* bl, int ldb,
                             float* Cf, int ldc,
                             bf16* Chi, bf16* Clo, int ldc2,
                             const float* bias, const float* res, int ldres,
                             int M, int Nc, int K, int act)
{
    dim3 grid(Nc / 128, M / 128);
    gemm_tc<<<grid, 256, GEMM_SMEM>>>(ah, al, lda, bh, bl, ldb, Cf, ldc,
                                      Chi, Clo, ldc2, bias, res, ldres, K, act);
}

extern "C" void kernel_launch(void* const* d_in, const int* in_sizes, int n_in,
                              void* d_out, int out_size)
{
    const float* x       = (const float*)d_in[0];
    const float* old_fii = (const float*)d_in[1];
    const float* ng1_w1 = (const float*)d_in[2];
    const float* ng1_b1 = (const float*)d_in[3];
    const float* ng1_w2 = (const float*)d_in[4];
    const float* ng1_b2 = (const float*)d_in[5];
    const float* ng2_w1 = (const float*)d_in[6];
    const float* ng2_b1 = (const float*)d_in[7];
    const float* ng2_w2 = (const float*)d_in[8];
    const float* ng2_b2 = (const float*)d_in[9];
    const float* ngo_w1 = (const float*)d_in[10];
    const float* ngo_b1 = (const float*)d_in[11];
    const float* ngo_w2 = (const float*)d_in[12];
    const float* ngo_b2 = (const float*)d_in[13];
    const float* lin1_w0 = (const float*)d_in[14];
    const float* lin1_b0 = (const float*)d_in[15];
    const float* lin1_w1 = (const float*)d_in[16];
    const float* lin2_w0 = (const float*)d_in[17];
    const float* lin2_b0 = (const float*)d_in[18];
    const float* lin2_w1 = (const float*)d_in[19];
    const float* lin3_w0 = (const float*)d_in[20];
    const float* lin3_b0 = (const float*)d_in[21];
    const float* lin3_w1 = (const float*)d_in[22];
    const float* tp_w    = (const float*)d_in[23];
    float* out = (float*)d_out;

    cudaFuncSetAttribute(gemm_tc, cudaFuncAttributeMaxDynamicSharedMemorySize, GEMM_SMEM);

    bf16 *F0h,*F0l,*H1h,*H1l,*H2h,*H2l,*H3h,*H3l,*G1h,*G1l,*G2h,*G2l,*G3h,*G3l,
         *VG1h,*VG1l,*VG2h,*VG2l,*VG3h,*VG3l,*F0th,*F0tl,*Whi,*Wlo;
    float *V,*Vt,*SL,*SR,*VL,*VR,*VO3;
    cudaGetSymbolAddress((void**)&F0h,  g_F0h);  cudaGetSymbolAddress((void**)&F0l,  g_F0l);
    cudaGetSymbolAddress((void**)&H1h,  g_H1h);  cudaGetSymbolAddress((void**)&H1l,  g_H1l);
    cudaGetSymbolAddress((void**)&H2h,  g_H2h);  cudaGetSymbolAddress((void**)&H2l,  g_H2l);
    cudaGetSymbolAddress((void**)&H3h,  g_H3h);  cudaGetSymbolAddress((void**)&H3l,  g_H3l);
    cudaGetSymbolAddress((void**)&G1h,  g_G1h);  cudaGetSymbolAddress((void**)&G1l,  g_G1l);
    cudaGetSymbolAddress((void**)&G2h,  g_G2h);  cudaGetSymbolAddress((void**)&G2l,  g_G2l);
    cudaGetSymbolAddress((void**)&G3h,  g_G3h);  cudaGetSymbolAddress((void**)&G3l,  g_G3l);
    cudaGetSymbolAddress((void**)&VG1h, g_VG1h); cudaGetSymbolAddress((void**)&VG1l, g_VG1l);
    cudaGetSymbolAddress((void**)&VG2h, g_VG2h); cudaGetSymbolAddress((void**)&VG2l, g_VG2l);
    cudaGetSymbolAddress((void**)&VG3h, g_VG3h); cudaGetSymbolAddress((void**)&VG3l, g_VG3l);
    cudaGetSymbolAddress((void**)&F0th, g_F0th); cudaGetSymbolAddress((void**)&F0tl, g_F0tl);
    cudaGetSymbolAddress((void**)&Whi,  g_Whi);  cudaGetSymbolAddress((void**)&Wlo,  g_Wlo);
    cudaGetSymbolAddress((void**)&V,    g_V);
    cudaGetSymbolAddress((void**)&Vt,   g_Vt);
    cudaGetSymbolAddress((void**)&SL,   g_SL);
    cudaGetSymbolAddress((void**)&SR,   g_SR);
    cudaGetSymbolAddress((void**)&VL,   g_VL);
    cudaGetSymbolAddress((void**)&VR,   g_VR);
    cudaGetSymbolAddress((void**)&VO3,  g_VO3);

    // weight scratch offsets (elements)
    const int OB = 262144;  // 512*512
    const int OS = 65536;   // 256*256
    const int o_ng1w1 = 0,        o_ng2w1 = OB,       o_ng1w2 = 2*OB,
              o_ng2w2 = 3*OB,     o_ngow1 = 4*OB,     o_ngow2 = 5*OB;
    const int o_l1w0 = 6*OB,          o_l1w1 = 6*OB + OS,   o_l2w0 = 6*OB + 2*OS,
              o_l2w1 = 6*OB + 3*OS,   o_l3w0 = 6*OB + 4*OS, o_l3w1 = 6*OB + 5*OS;

    const float inv16 = 0.0625f;  // 1/sqrt(256), folded into lin weights

    // ---- convert weights once (2 batched launches) ----
    {
        const int T = 256;
        int nb = (6 * 512 * 512 + T - 1) / T;
        convert_w6<<<nb, T>>>(ng1_w1, ng2_w1, ng1_w2, ng2_w2, ngo_w1, ngo_w2,
                              Whi, Wlo, 512, 512, 1.f, OB);
        int ns = (6 * 256 * 256 + T - 1) / T;
        convert_w6<<<ns, T>>>(lin1_w0, lin1_w1, lin2_w0, lin2_w1, lin3_w0, lin3_w1,
                              Whi + 6 * OB, Wlo + 6 * OB, 256, 256, inv16, OS);
    }

    // Stage 1: prep
    prep_kernel<<<NN, 256>>>(x, F0h, F0l, V);

    // Stage 2: NormGate MLPs (left/right) — H and G stored hi/lo only
    launch_tc(F0h, F0l, 512, Whi + o_ng1w1, Wlo + o_ng1w1, 512,
              nullptr, 0, H1h, H1l, 512, ng1_b1, nullptr, 0, NN, 512, 512, 1);
    launch_tc(F0h, F0l, 512, Whi + o_ng2w1, Wlo + o_ng2w1, 512,
              nullptr, 0, H2h, H2l, 512, ng2_b1, nullptr, 0, NN, 512, 512, 1);
    launch_tc(H1h, H1l, 512, Whi + o_ng1w2, Wlo + o_ng1w2, 512,
              nullptr, 0, G1h, G1l, 512, ng1_b2, nullptr, 0, NN, 512, 512, 0);
    launch_tc(H2h, H2l, 512, Whi + o_ng2w2, Wlo + o_ng2w2, 512,
              nullptr, 0, G2h, G2l, 512, ng2_b2, nullptr, 0, NN, 512, 512, 0);

    // Stage 3: gate vectors (hi/lo out)
    gate_kernel<<<NN * 3, 256>>>(V, G1h, G1l, VG1h, VG1l);
    gate_kernel<<<NN * 3, 256>>>(V, G2h, G2l, VG2h, VG2l);

    // Stage 4: irrep linears (fp32 out for tp)
    launch_tc(G1h,  G1l,  512, Whi + o_l1w0, Wlo + o_l1w0, 256,
              SL, 256, nullptr, nullptr, 0, lin1_b0, nullptr, 0, NN,     256, 256, 0);
    launch_tc(VG1h, VG1l, 256, Whi + o_l1w1, Wlo + o_l1w1, 256,
              VL, 256, nullptr, nullptr, 0, nullptr, nullptr, 0, 3 * NN, 256, 256, 0);
    launch_tc(G2h,  G2l,  512, Whi + o_l2w0, Wlo + o_l2w0, 256,
              SR, 256, nullptr, nullptr, 0, lin2_b0, nullptr, 0, NN,     256, 256, 0);
    launch_tc(VG2h, VG2l, 256, Whi + o_l2w1, Wlo + o_l2w1, 256,
              VR, 256, nullptr, nullptr, 0, nullptr, nullptr, 0, 3 * NN, 256, 256, 0);

    // Stage 5: tensor product + resnet (F0t hi/lo, Vt fp32)
    tp_kernel<<<NN, 256>>>(SL, VL, SR, VR, x, V, tp_w, F0th, F0tl, Vt);

    // Stage 6: output NormGate
    launch_tc(F0th, F0tl, 512, Whi + o_ngow1, Wlo + o_ngow1, 512,
              nullptr, 0, H3h, H3l, 512, ngo_b1, nullptr, 0, NN, 512, 512, 1);
    launch_tc(H3h,  H3l,  512, Whi + o_ngow2, Wlo + o_ngow2, 512,
              nullptr, 0, G3h, G3l, 512, ngo_b2, nullptr, 0, NN, 512, 512, 0);
    gate_kernel<<<NN * 3, 256>>>(Vt, G3h, G3l, VG3h, VG3l);

    // Stage 7: final irrep linear + old_fii residual
    launch_tc(G3h,  G3l,  512, Whi + o_l3w0, Wlo + o_l3w0, 256,
              out, 1024, nullptr, nullptr, 0, lin3_b0, old_fii, 1024, NN, 256, 256, 0);
    launch_tc(VG3h, VG3l, 256, Whi + o_l3w1, Wlo + o_l3w1, 256,
              VO3, 256, nullptr, nullptr, 0, nullptr, nullptr, 0, 3 * NN, 256, 256, 0);
    final_kernel<<<NN * 3, 256>>>(VO3, old_fii, out);
}